// round 1
// baseline (speedup 1.0000x reference)
#include <cuda_runtime.h>
#include <math.h>

#define CC     512
#define T_LEN  2048
#define BATCH  4
#define NH     8
#define HD     64

// Scratch (allocation-free rule: __device__ globals)
__device__ float g_qkv[(size_t)BATCH * 3 * CC * T_LEN];   // [b][3C][T]  48 MB
__device__ float g_att[(size_t)BATCH * CC * T_LEN];       // [b][C][T]   16 MB

// ---------------------------------------------------------------------------
// GEMM: C[z] = A[M,K] * B[z][K,N] + bias[m] (+ res[z][m][n])
// 128x128 block, BK=16, 256 threads, 8x8 microtile (split-N for bank-free LDS)
// ---------------------------------------------------------------------------
template<bool RES>
__global__ void __launch_bounds__(256) gemm_bias(
    const float* __restrict__ A, const float* __restrict__ B,
    const float* __restrict__ bias, const float* __restrict__ res,
    float* __restrict__ C, int M, int N, int K)
{
    __shared__ float As[16][128];
    __shared__ float Bs[16][128];

    const int z  = blockIdx.z;
    const float* Bz = B + (size_t)z * K * N;
    float*       Cz = C + (size_t)z * M * N;
    const int m0 = blockIdx.y * 128;
    const int n0 = blockIdx.x * 128;
    const int tid = threadIdx.x;
    const int tx = tid & 15;
    const int ty = tid >> 4;

    float acc[8][8];
#pragma unroll
    for (int i = 0; i < 8; i++)
#pragma unroll
        for (int j = 0; j < 8; j++) acc[i][j] = 0.f;

    for (int k0 = 0; k0 < K; k0 += 16) {
#pragma unroll
        for (int l = 0; l < 2; l++) {
            int f   = tid + l * 256;          // 0..511
            int row = f >> 2;                 // 0..127 (m)
            int kc  = (f & 3) << 2;           // 0,4,8,12
            float4 va = *(const float4*)(A + (size_t)(m0 + row) * K + k0 + kc);
            As[kc + 0][row] = va.x;
            As[kc + 1][row] = va.y;
            As[kc + 2][row] = va.z;
            As[kc + 3][row] = va.w;
            int brow = f >> 5;                // 0..15 (k)
            int bcol = (f & 31) << 2;         // 0..124
            *(float4*)&Bs[brow][bcol] =
                *(const float4*)(Bz + (size_t)(k0 + brow) * N + n0 + bcol);
        }
        __syncthreads();
#pragma unroll
        for (int kk = 0; kk < 16; kk++) {
            float a[8], bb[8];
            *(float4*)&a[0]  = *(float4*)&As[kk][ty * 8];
            *(float4*)&a[4]  = *(float4*)&As[kk][ty * 8 + 4];
            *(float4*)&bb[0] = *(float4*)&Bs[kk][tx * 4];
            *(float4*)&bb[4] = *(float4*)&Bs[kk][64 + tx * 4];
#pragma unroll
            for (int i = 0; i < 8; i++)
#pragma unroll
                for (int j = 0; j < 8; j++)
                    acc[i][j] = fmaf(a[i], bb[j], acc[i][j]);
        }
        __syncthreads();
    }

#pragma unroll
    for (int i = 0; i < 8; i++) {
        int m = m0 + ty * 8 + i;
        float bv = bias[m];
        size_t base = (size_t)m * N + n0;
#pragma unroll
        for (int g = 0; g < 2; g++) {
            int nc = g * 64 + tx * 4;
            float4 w;
            w.x = acc[i][g * 4 + 0] + bv;
            w.y = acc[i][g * 4 + 1] + bv;
            w.z = acc[i][g * 4 + 2] + bv;
            w.w = acc[i][g * 4 + 3] + bv;
            if (RES) {
                float4 r = *(const float4*)(res + (size_t)z * M * N + base + nc);
                w.x += r.x; w.y += r.y; w.z += r.z; w.w += r.w;
            }
            *(float4*)(Cz + base + nc) = w;
        }
    }
}

// ---------------------------------------------------------------------------
// Flash-style attention. Block = (b, h, 64 query positions). 256 threads.
// smem: Q[64][64], KV[64][128] (K then V reuse), S[64][128], stats[3][64].
// ---------------------------------------------------------------------------
#define BT 64
#define BS 128
#define SQ_F   (HD * BT)      // 4096
#define SKV_F  (HD * BS)      // 8192
#define SS_F   (BT * BS)      // 8192
#define ATTN_SMEM_FLOATS (SQ_F + SKV_F + SS_F + 3 * BT)
#define ATTN_SMEM_BYTES  (ATTN_SMEM_FLOATS * 4)

__global__ void __launch_bounds__(256, 2) attn_fwd()
{
    extern __shared__ float sm[];
    float* sQ  = sm;               // [HD][BT]
    float* sKV = sQ + SQ_F;        // [HD][BS]
    float* sS  = sKV + SKV_F;      // [BT][BS]
    float* sM  = sS + SS_F;
    float* sL  = sM + BT;
    float* sF  = sL + BT;

    const int t0   = blockIdx.x * BT;
    const int h    = blockIdx.y;
    const int b    = blockIdx.z;
    const int tid  = threadIdx.x;
    const int tx   = tid & 15;
    const int ty   = tid >> 4;
    const int lane = tid & 31;
    const int warp = tid >> 5;

    const float* qg = g_qkv + ((size_t)b * 3 * CC + h * HD) * T_LEN;
    const float* kg = qg + (size_t)CC * T_LEN;
    const float* vg = kg + (size_t)CC * T_LEN;

    // Q tile [HD][BT]
#pragma unroll
    for (int l = 0; l < 4; l++) {
        int f = tid + l * 256;
        int row = f >> 4;
        int col = (f & 15) << 2;
        *(float4*)&sQ[row * BT + col] =
            *(const float4*)(qg + (size_t)row * T_LEN + t0 + col);
    }
    if (tid < BT) { sM[tid] = -INFINITY; sL[tid] = 0.f; }

    float o[4][4];
#pragma unroll
    for (int i = 0; i < 4; i++)
#pragma unroll
        for (int j = 0; j < 4; j++) o[i][j] = 0.f;

    const float scale = 0.044194173824159216f;   // 512^-0.5 (full C, per reference)

    __syncthreads();

    for (int s0 = 0; s0 < T_LEN; s0 += BS) {
        // K tile -> sKV
#pragma unroll
        for (int l = 0; l < 8; l++) {
            int f = tid + l * 256;
            int row = f >> 5;
            int col = (f & 31) << 2;
            *(float4*)&sKV[row * BS + col] =
                *(const float4*)(kg + (size_t)row * T_LEN + s0 + col);
        }
        __syncthreads();

        // S[tt][ss] = Q^T K : 4t x 8s microtile
        float sa[4][8];
#pragma unroll
        for (int i = 0; i < 4; i++)
#pragma unroll
            for (int j = 0; j < 8; j++) sa[i][j] = 0.f;
#pragma unroll
        for (int dd = 0; dd < HD; dd++) {
            float4 qv = *(float4*)&sQ[dd * BT + ty * 4];
            float4 ka = *(float4*)&sKV[dd * BS + tx * 4];
            float4 kb = *(float4*)&sKV[dd * BS + 64 + tx * 4];
            float qa[4] = {qv.x, qv.y, qv.z, qv.w};
            float kk[8] = {ka.x, ka.y, ka.z, ka.w, kb.x, kb.y, kb.z, kb.w};
#pragma unroll
            for (int i = 0; i < 4; i++)
#pragma unroll
                for (int j = 0; j < 8; j++)
                    sa[i][j] = fmaf(qa[i], kk[j], sa[i][j]);
        }
        __syncthreads();   // everyone done reading K (sKV) and prior sS

        // write scaled S; then load V into sKV
#pragma unroll
        for (int i = 0; i < 4; i++) {
            int r = ty * 4 + i;
            float4 w0 = {sa[i][0] * scale, sa[i][1] * scale, sa[i][2] * scale, sa[i][3] * scale};
            float4 w1 = {sa[i][4] * scale, sa[i][5] * scale, sa[i][6] * scale, sa[i][7] * scale};
            *(float4*)&sS[r * BS + tx * 4]      = w0;
            *(float4*)&sS[r * BS + 64 + tx * 4] = w1;
        }
#pragma unroll
        for (int l = 0; l < 8; l++) {
            int f = tid + l * 256;
            int row = f >> 5;
            int col = (f & 31) << 2;
            *(float4*)&sKV[row * BS + col] =
                *(const float4*)(vg + (size_t)row * T_LEN + s0 + col);
        }
        __syncthreads();

        // online softmax: warp w owns rows w*8 .. w*8+7
#pragma unroll
        for (int i = 0; i < 8; i++) {
            int r = warp * 8 + i;
            float* row = sS + r * BS;
            float v0 = row[lane], v1 = row[lane + 32], v2 = row[lane + 64], v3 = row[lane + 96];
            float mx = fmaxf(fmaxf(v0, v1), fmaxf(v2, v3));
#pragma unroll
            for (int off = 16; off > 0; off >>= 1)
                mx = fmaxf(mx, __shfl_xor_sync(0xffffffffu, mx, off));
            float mOld = sM[r];
            float mNew = fmaxf(mOld, mx);
            float p0 = __expf(v0 - mNew);
            float p1 = __expf(v1 - mNew);
            float p2 = __expf(v2 - mNew);
            float p3 = __expf(v3 - mNew);
            row[lane] = p0; row[lane + 32] = p1; row[lane + 64] = p2; row[lane + 96] = p3;
            float s = (p0 + p1) + (p2 + p3);
#pragma unroll
            for (int off = 16; off > 0; off >>= 1)
                s += __shfl_xor_sync(0xffffffffu, s, off);
            if (lane == 0) {
                float fac = __expf(mOld - mNew);
                sF[r] = fac;
                sL[r] = sL[r] * fac + s;
                sM[r] = mNew;
            }
        }
        __syncthreads();

        // rescale O, then O += P V^T (lane-rotated s chunks: bank-conflict free)
#pragma unroll
        for (int i = 0; i < 4; i++) {
            float fr = sF[ty * 4 + i];
#pragma unroll
            for (int j = 0; j < 4; j++) o[i][j] *= fr;
        }
#pragma unroll
        for (int ci = 0; ci < 32; ci++) {
            int sc = ((ci + tx) & 31) << 2;
            float4 p4[4], v4[4];
#pragma unroll
            for (int i = 0; i < 4; i++)
                p4[i] = *(float4*)&sS[(ty * 4 + i) * BS + sc];
#pragma unroll
            for (int j = 0; j < 4; j++)
                v4[j] = *(float4*)&sKV[(tx * 4 + j) * BS + sc];
#pragma unroll
            for (int i = 0; i < 4; i++)
#pragma unroll
                for (int j = 0; j < 4; j++) {
                    o[i][j] = fmaf(p4[i].x, v4[j].x, o[i][j]);
                    o[i][j] = fmaf(p4[i].y, v4[j].y, o[i][j]);
                    o[i][j] = fmaf(p4[i].z, v4[j].z, o[i][j]);
                    o[i][j] = fmaf(p4[i].w, v4[j].w, o[i][j]);
                }
        }
        __syncthreads();   // before next tile overwrites sKV/sS
    }

    // normalize + write out[b][h*64+c][t]
    float inv[4];
#pragma unroll
    for (int i = 0; i < 4; i++) inv[i] = 1.f / sL[ty * 4 + i];
    float* og = g_att + ((size_t)b * CC + h * HD) * T_LEN;
#pragma unroll
    for (int j = 0; j < 4; j++) {
        int c = tx * 4 + j;
        float4 w = { o[0][j] * inv[0], o[1][j] * inv[1], o[2][j] * inv[2], o[3][j] * inv[3] };
        *(float4*)(og + (size_t)c * T_LEN + t0 + ty * 4) = w;
    }
}

// ---------------------------------------------------------------------------
extern "C" void kernel_launch(void* const* d_in, const int* in_sizes, int n_in,
                              void* d_out, int out_size)
{
    const float* x      = (const float*)d_in[0];
    const float* qkv_w  = (const float*)d_in[1];
    const float* qkv_b  = (const float*)d_in[2];
    const float* proj_w = (const float*)d_in[3];
    const float* proj_b = (const float*)d_in[4];
    float* out = (float*)d_out;

    float *qkv_ptr = nullptr, *att_ptr = nullptr;
    cudaGetSymbolAddress((void**)&qkv_ptr, g_qkv);
    cudaGetSymbolAddress((void**)&att_ptr, g_att);
    cudaFuncSetAttribute((const void*)attn_fwd,
                         cudaFuncAttributeMaxDynamicSharedMemorySize, ATTN_SMEM_BYTES);

    dim3 blk(256);
    // 1) qkv = W_qkv @ x + b
    gemm_bias<false><<<dim3(T_LEN / 128, (3 * CC) / 128, BATCH), blk>>>(
        qkv_w, x, qkv_b, nullptr, qkv_ptr, 3 * CC, T_LEN, CC);
    // 2) attention
    attn_fwd<<<dim3(T_LEN / BT, NH, BATCH), blk, ATTN_SMEM_BYTES>>>();
    // 3) out = x + W_proj @ att + b
    gemm_bias<true><<<dim3(T_LEN / 128, CC / 128, BATCH), blk>>>(
        proj_w, att_ptr, proj_b, x, out, CC, T_LEN, CC);
}

// round 3
// speedup vs baseline: 1.6256x; 1.6256x over previous
#include <cuda_runtime.h>
#include <cuda_bf16.h>
#include <math.h>
#include <stdint.h>

#define CC     512
#define T_LEN  2048
#define BATCH  4
#define NH     8
#define HD     64

// Scratch (allocation-free rule: __device__ globals)
__device__ float g_qkv[(size_t)BATCH * 3 * CC * T_LEN];   // [b][3C][T]
__device__ float g_att[(size_t)BATCH * CC * T_LEN];       // [b][C][T]

// ===========================================================================
// helpers
// ===========================================================================
__device__ __forceinline__ uint32_t smem_u32(const void* p) {
    uint32_t a;
    asm("{ .reg .u64 t; cvta.to.shared.u64 t, %1; cvt.u32.u64 %0, t; }" : "=r"(a) : "l"(p));
    return a;
}
__device__ __forceinline__ uint32_t pk_bf2(__nv_bfloat16 a, __nv_bfloat16 b) {
    __nv_bfloat162 t(a, b);
    return *reinterpret_cast<uint32_t*>(&t);
}
// split (x,y) into packed bf16 hi and lo
__device__ __forceinline__ void split2(float x, float y, uint32_t& hi, uint32_t& lo) {
    __nv_bfloat16 xh = __float2bfloat16(x), yh = __float2bfloat16(y);
    __nv_bfloat16 xl = __float2bfloat16(x - __bfloat162float(xh));
    __nv_bfloat16 yl = __float2bfloat16(y - __bfloat162float(yh));
    hi = pk_bf2(xh, yh);
    lo = pk_bf2(xl, yl);
}

__device__ __forceinline__ void ldsm4(uint32_t& r0, uint32_t& r1, uint32_t& r2, uint32_t& r3,
                                      uint32_t addr) {
    asm volatile("ldmatrix.sync.aligned.m8n8.x4.shared.b16 {%0,%1,%2,%3}, [%4];"
                 : "=r"(r0), "=r"(r1), "=r"(r2), "=r"(r3) : "r"(addr));
}
__device__ __forceinline__ void ldsm4t(uint32_t& r0, uint32_t& r1, uint32_t& r2, uint32_t& r3,
                                       uint32_t addr) {
    asm volatile("ldmatrix.sync.aligned.m8n8.x4.trans.shared.b16 {%0,%1,%2,%3}, [%4];"
                 : "=r"(r0), "=r"(r1), "=r"(r2), "=r"(r3) : "r"(addr));
}
__device__ __forceinline__ void mma16816(float* c, uint32_t a0, uint32_t a1, uint32_t a2,
                                         uint32_t a3, uint32_t b0, uint32_t b1) {
    asm volatile(
        "mma.sync.aligned.m16n8k16.row.col.f32.bf16.bf16.f32 "
        "{%0,%1,%2,%3}, {%4,%5,%6,%7}, {%8,%9}, {%0,%1,%2,%3};"
        : "+f"(c[0]), "+f"(c[1]), "+f"(c[2]), "+f"(c[3])
        : "r"(a0), "r"(a1), "r"(a2), "r"(a3), "r"(b0), "r"(b1));
}

// ===========================================================================
// GEMM: C[z] = A[M,K] * B[z][K,N] + bias[m] (+ res[z][m][n])  (fp32, from R1)
// ===========================================================================
template<bool RES>
__global__ void __launch_bounds__(256) gemm_bias(
    const float* __restrict__ A, const float* __restrict__ B,
    const float* __restrict__ bias, const float* __restrict__ res,
    float* __restrict__ C, int M, int N, int K)
{
    __shared__ float As[16][128];
    __shared__ float Bs[16][128];

    const int z  = blockIdx.z;
    const float* Bz = B + (size_t)z * K * N;
    float*       Cz = C + (size_t)z * M * N;
    const int m0 = blockIdx.y * 128;
    const int n0 = blockIdx.x * 128;
    const int tid = threadIdx.x;
    const int tx = tid & 15;
    const int ty = tid >> 4;

    float acc[8][8];
#pragma unroll
    for (int i = 0; i < 8; i++)
#pragma unroll
        for (int j = 0; j < 8; j++) acc[i][j] = 0.f;

    for (int k0 = 0; k0 < K; k0 += 16) {
#pragma unroll
        for (int l = 0; l < 2; l++) {
            int f   = tid + l * 256;
            int row = f >> 2;
            int kc  = (f & 3) << 2;
            float4 va = *(const float4*)(A + (size_t)(m0 + row) * K + k0 + kc);
            As[kc + 0][row] = va.x;
            As[kc + 1][row] = va.y;
            As[kc + 2][row] = va.z;
            As[kc + 3][row] = va.w;
            int brow = f >> 5;
            int bcol = (f & 31) << 2;
            *(float4*)&Bs[brow][bcol] =
                *(const float4*)(Bz + (size_t)(k0 + brow) * N + n0 + bcol);
        }
        __syncthreads();
#pragma unroll
        for (int kk = 0; kk < 16; kk++) {
            float a[8], bb[8];
            *(float4*)&a[0]  = *(float4*)&As[kk][ty * 8];
            *(float4*)&a[4]  = *(float4*)&As[kk][ty * 8 + 4];
            *(float4*)&bb[0] = *(float4*)&Bs[kk][tx * 4];
            *(float4*)&bb[4] = *(float4*)&Bs[kk][64 + tx * 4];
#pragma unroll
            for (int i = 0; i < 8; i++)
#pragma unroll
                for (int j = 0; j < 8; j++)
                    acc[i][j] = fmaf(a[i], bb[j], acc[i][j]);
        }
        __syncthreads();
    }

#pragma unroll
    for (int i = 0; i < 8; i++) {
        int m = m0 + ty * 8 + i;
        float bv = bias[m];
        size_t base = (size_t)m * N + n0;
#pragma unroll
        for (int g = 0; g < 2; g++) {
            int nc = g * 64 + tx * 4;
            float4 w;
            w.x = acc[i][g * 4 + 0] + bv;
            w.y = acc[i][g * 4 + 1] + bv;
            w.z = acc[i][g * 4 + 2] + bv;
            w.w = acc[i][g * 4 + 3] + bv;
            if (RES) {
                float4 r = *(const float4*)(res + (size_t)z * M * N + base + nc);
                w.x += r.x; w.y += r.y; w.z += r.z; w.w += r.w;
            }
            *(float4*)(Cz + base + nc) = w;
        }
    }
}

// ===========================================================================
// Attention via mma.sync bf16 (3-term hi/lo compensation)
// CTA: 128 query rows, 8 warps (16 rows each), s-tiles of 64.
// ===========================================================================
#define BT2 128
#define BS2 64
#define NIT (T_LEN / BS2)
#define RSTR 72                     // bf16 per smem row => 144B (16B-aligned, bank-clean)

#define SM_QHI 0
#define SM_QLO 18432
#define SM_KHI 36864
#define SM_KLO 46080
#define SM_VHI 55296
#define SM_VLO 64512
#define SM_OST 36864                // output staging reuses K/V region
#define ATTN_SMEM 73728

__global__ void __launch_bounds__(256, 2) attn_mma()
{
    extern __shared__ char sm[];
    const int tid  = threadIdx.x;
    const int wid  = tid >> 5;
    const int lane = tid & 31;
    const int t0 = blockIdx.x * BT2;
    const int h  = blockIdx.y;
    const int b  = blockIdx.z;

    const float* qg = g_qkv + ((size_t)b * 3 * CC + h * HD) * T_LEN;
    const float* kg = qg + (size_t)CC * T_LEN;
    const float* vg = kg + (size_t)CC * T_LEN;

    const float scale = 0.044194173824159216f;   // 512^-0.5 (full C, per reference)

    // ---- load Q (transpose [d][t] -> [t][d], scale, hi/lo split) ----
#pragma unroll
    for (int l = 0; l < 8; ++l) {
        int f  = tid + l * 256;
        int d  = f >> 5;
        int t4 = (f & 31) << 2;
        float4 v = *(const float4*)(qg + (size_t)d * T_LEN + t0 + t4);
        float vv[4] = {v.x * scale, v.y * scale, v.z * scale, v.w * scale};
#pragma unroll
        for (int e = 0; e < 4; ++e) {
            __nv_bfloat16 hi = __float2bfloat16(vv[e]);
            __nv_bfloat16 lo = __float2bfloat16(vv[e] - __bfloat162float(hi));
            *(__nv_bfloat16*)(sm + SM_QHI + (size_t)(t4 + e) * 144 + d * 2) = hi;
            *(__nv_bfloat16*)(sm + SM_QLO + (size_t)(t4 + e) * 144 + d * 2) = lo;
        }
    }

    float oacc[32];
#pragma unroll
    for (int i = 0; i < 32; ++i) oacc[i] = 0.f;
    float m_r1 = -INFINITY, m_r2 = -INFINITY, l_r1 = 0.f, l_r2 = 0.f;

    const uint32_t smb = smem_u32(sm);
    const int lr = lane & 15;
    const int lc = lane >> 4;
    const uint32_t qa_hi = smb + SM_QHI + (uint32_t)(wid * 16 + lr) * 144 + lc * 16;
    const uint32_t qa_lo = qa_hi + (SM_QLO - SM_QHI);
    const uint32_t kb_hi = smb + SM_KHI + (uint32_t)lr * 144 + lc * 16;
    const uint32_t kb_lo = kb_hi + (SM_KLO - SM_KHI);
    const uint32_t vb_hi = smb + SM_VHI + (uint32_t)lr * 144 + lc * 16;
    const uint32_t vb_lo = vb_hi + (SM_VLO - SM_VHI);

    __syncthreads();

    for (int it = 0; it < NIT; ++it) {
        const int s0 = it * BS2;

        // ---- K tile [d=64][s=64] (direct), V tile transposed -> [s][d] ----
#pragma unroll
        for (int l = 0; l < 4; ++l) {
            int f  = tid + l * 256;
            int d  = f >> 4;
            int s4 = (f & 15) << 2;
            float4 v = *(const float4*)(kg + (size_t)d * T_LEN + s0 + s4);
            uint32_t h0, l0, h1, l1;
            split2(v.x, v.y, h0, l0);
            split2(v.z, v.w, h1, l1);
            *(uint2*)(sm + SM_KHI + (size_t)d * 144 + s4 * 2) = make_uint2(h0, h1);
            *(uint2*)(sm + SM_KLO + (size_t)d * 144 + s4 * 2) = make_uint2(l0, l1);
        }
#pragma unroll
        for (int l = 0; l < 4; ++l) {
            int f  = tid + l * 256;
            int d  = f >> 4;
            int s4 = (f & 15) << 2;
            float4 v = *(const float4*)(vg + (size_t)d * T_LEN + s0 + s4);
            float vv[4] = {v.x, v.y, v.z, v.w};
#pragma unroll
            for (int e = 0; e < 4; ++e) {
                __nv_bfloat16 hi = __float2bfloat16(vv[e]);
                __nv_bfloat16 lo = __float2bfloat16(vv[e] - __bfloat162float(hi));
                *(__nv_bfloat16*)(sm + SM_VHI + (size_t)(s4 + e) * 144 + d * 2) = hi;
                *(__nv_bfloat16*)(sm + SM_VLO + (size_t)(s4 + e) * 144 + d * 2) = lo;
            }
        }
        __syncthreads();

        // ---- S = Q K^T  (rows t, cols s; fp32 accum) ----
        float sacc[32];
#pragma unroll
        for (int i = 0; i < 32; ++i) sacc[i] = 0.f;
#pragma unroll
        for (int ks = 0; ks < 4; ++ks) {
            uint32_t qh0, qh1, qh2, qh3, ql0, ql1, ql2, ql3;
            ldsm4(qh0, qh1, qh2, qh3, qa_hi + ks * 32);
            ldsm4(ql0, ql1, ql2, ql3, qa_lo + ks * 32);
#pragma unroll
            for (int np = 0; np < 4; ++np) {
                uint32_t bh0, bh1, bh2, bh3, bl0, bl1, bl2, bl3;
                ldsm4t(bh0, bh1, bh2, bh3, kb_hi + ks * 2304 + np * 32);
                ldsm4t(bl0, bl1, bl2, bl3, kb_lo + ks * 2304 + np * 32);
                float* c0 = &sacc[np * 8];
                float* c1 = &sacc[np * 8 + 4];
                mma16816(c0, qh0, qh1, qh2, qh3, bh0, bh1);
                mma16816(c0, qh0, qh1, qh2, qh3, bl0, bl1);
                mma16816(c0, ql0, ql1, ql2, ql3, bh0, bh1);
                mma16816(c1, qh0, qh1, qh2, qh3, bh2, bh3);
                mma16816(c1, qh0, qh1, qh2, qh3, bl2, bl3);
                mma16816(c1, ql0, ql1, ql2, ql3, bh2, bh3);
            }
        }

        // ---- online softmax (rows r = lane>>2 and r+8 of warp tile) ----
        float nm1 = -INFINITY, nm2 = -INFINITY;
#pragma unroll
        for (int j = 0; j < 8; ++j) {
            nm1 = fmaxf(nm1, fmaxf(sacc[4 * j],     sacc[4 * j + 1]));
            nm2 = fmaxf(nm2, fmaxf(sacc[4 * j + 2], sacc[4 * j + 3]));
        }
        nm1 = fmaxf(nm1, __shfl_xor_sync(0xffffffffu, nm1, 1));
        nm1 = fmaxf(nm1, __shfl_xor_sync(0xffffffffu, nm1, 2));
        nm2 = fmaxf(nm2, __shfl_xor_sync(0xffffffffu, nm2, 1));
        nm2 = fmaxf(nm2, __shfl_xor_sync(0xffffffffu, nm2, 2));
        const float mn1 = fmaxf(m_r1, nm1);
        const float mn2 = fmaxf(m_r2, nm2);
        const float a1 = __expf(m_r1 - mn1);
        const float a2 = __expf(m_r2 - mn2);
        float s1 = 0.f, s2 = 0.f;
#pragma unroll
        for (int j = 0; j < 8; ++j) {
            float e0 = __expf(sacc[4 * j]     - mn1);
            float e1 = __expf(sacc[4 * j + 1] - mn1);
            float e2 = __expf(sacc[4 * j + 2] - mn2);
            float e3 = __expf(sacc[4 * j + 3] - mn2);
            sacc[4 * j] = e0; sacc[4 * j + 1] = e1; sacc[4 * j + 2] = e2; sacc[4 * j + 3] = e3;
            s1 += e0 + e1;
            s2 += e2 + e3;
        }
        s1 += __shfl_xor_sync(0xffffffffu, s1, 1);
        s1 += __shfl_xor_sync(0xffffffffu, s1, 2);
        s2 += __shfl_xor_sync(0xffffffffu, s2, 1);
        s2 += __shfl_xor_sync(0xffffffffu, s2, 2);
        l_r1 = l_r1 * a1 + s1;
        l_r2 = l_r2 * a2 + s2;
        m_r1 = mn1;
        m_r2 = mn2;
#pragma unroll
        for (int j = 0; j < 8; ++j) {
            oacc[4 * j]     *= a1;
            oacc[4 * j + 1] *= a1;
            oacc[4 * j + 2] *= a2;
            oacc[4 * j + 3] *= a2;
        }

        // ---- O += P V^T  (P fragments repacked straight from sacc) ----
#pragma unroll
        for (int ks = 0; ks < 4; ++ks) {
            const float* sA = &sacc[8 * ks];
            uint32_t ph0, ph1, ph2, ph3, pl0, pl1, pl2, pl3;
            split2(sA[0], sA[1], ph0, pl0);
            split2(sA[2], sA[3], ph1, pl1);
            split2(sA[4], sA[5], ph2, pl2);
            split2(sA[6], sA[7], ph3, pl3);
#pragma unroll
            for (int np = 0; np < 4; ++np) {
                uint32_t bh0, bh1, bh2, bh3, bl0, bl1, bl2, bl3;
                ldsm4t(bh0, bh1, bh2, bh3, vb_hi + ks * 2304 + np * 32);
                ldsm4t(bl0, bl1, bl2, bl3, vb_lo + ks * 2304 + np * 32);
                float* c0 = &oacc[np * 8];
                float* c1 = &oacc[np * 8 + 4];
                mma16816(c0, ph0, ph1, ph2, ph3, bh0, bh1);
                mma16816(c0, ph0, ph1, ph2, ph3, bl0, bl1);
                mma16816(c0, pl0, pl1, pl2, pl3, bh0, bh1);
                mma16816(c1, ph0, ph1, ph2, ph3, bh2, bh3);
                mma16816(c1, ph0, ph1, ph2, ph3, bl2, bl3);
                mma16816(c1, pl0, pl1, pl2, pl3, bh2, bh3);
            }
        }
        __syncthreads();
    }

    // ---- epilogue: normalize, stage [d][t] in smem, coalesced write ----
    {
        float* so = (float*)(sm + SM_OST);
        const float i1 = 1.f / l_r1;
        const float i2 = 1.f / l_r2;
        const int r  = lane >> 2;
        const int tw = wid * 16;
#pragma unroll
        for (int j = 0; j < 8; ++j) {
            int d0 = 8 * j + ((lane & 3) << 1);
            so[(size_t)d0 * 128 + tw + r]           = oacc[4 * j]     * i1;
            so[(size_t)(d0 + 1) * 128 + tw + r]     = oacc[4 * j + 1] * i1;
            so[(size_t)d0 * 128 + tw + r + 8]       = oacc[4 * j + 2] * i2;
            so[(size_t)(d0 + 1) * 128 + tw + r + 8] = oacc[4 * j + 3] * i2;
        }
        __syncthreads();
        float* og = g_att + ((size_t)b * CC + h * HD) * T_LEN;
#pragma unroll
        for (int l = 0; l < 8; ++l) {
            int f  = tid + l * 256;
            int c  = f >> 5;
            int t4 = (f & 31) << 2;
            *(float4*)(og + (size_t)c * T_LEN + t0 + t4) = *(float4*)&so[(size_t)c * 128 + t4];
        }
    }
}

// ===========================================================================
extern "C" void kernel_launch(void* const* d_in, const int* in_sizes, int n_in,
                              void* d_out, int out_size)
{
    const float* x      = (const float*)d_in[0];
    const float* qkv_w  = (const float*)d_in[1];
    const float* qkv_b  = (const float*)d_in[2];
    const float* proj_w = (const float*)d_in[3];
    const float* proj_b = (const float*)d_in[4];
    float* out = (float*)d_out;

    float *qkv_ptr = nullptr, *att_ptr = nullptr;
    cudaGetSymbolAddress((void**)&qkv_ptr, g_qkv);
    cudaGetSymbolAddress((void**)&att_ptr, g_att);
    cudaFuncSetAttribute((const void*)attn_mma,
                         cudaFuncAttributeMaxDynamicSharedMemorySize, ATTN_SMEM);

    // 1) qkv = W_qkv @ x + b
    gemm_bias<false><<<dim3(T_LEN / 128, (3 * CC) / 128, BATCH), 256>>>(
        qkv_w, x, qkv_b, nullptr, qkv_ptr, 3 * CC, T_LEN, CC);
    // 2) attention (mma.sync bf16, 3-term)
    attn_mma<<<dim3(T_LEN / BT2, NH, BATCH), 256, ATTN_SMEM>>>();
    // 3) out = x + W_proj @ att + b
    gemm_bias<true><<<dim3(T_LEN / 128, CC / 128, BATCH), 256>>>(
        proj_w, att_ptr, proj_b, x, out, CC, T_LEN, CC);
}

// round 4
// speedup vs baseline: 2.1939x; 1.3496x over previous
#include <cuda_runtime.h>
#include <cuda_bf16.h>
#include <math.h>
#include <stdint.h>

#define CC     512
#define T_LEN  2048
#define BATCH  4
#define NH     8
#define HD     64

// Scratch (allocation-free rule: __device__ globals)
__device__ float g_qkv[(size_t)BATCH * 3 * CC * T_LEN];   // [b][3C][T]
__device__ float g_att[(size_t)BATCH * CC * T_LEN];       // [b][C][T]

// bf16 hi/lo pre-split operands
#define W_ELEMS (3 * CC * CC + CC * CC)          // qkv_w then proj_w
#define X_ELEMS ((size_t)BATCH * CC * T_LEN)
__device__ __nv_bfloat16 g_whi[W_ELEMS];
__device__ __nv_bfloat16 g_wlo[W_ELEMS];
__device__ __nv_bfloat16 g_xhi[X_ELEMS];
__device__ __nv_bfloat16 g_xlo[X_ELEMS];

// ===========================================================================
// helpers
// ===========================================================================
__device__ __forceinline__ uint32_t smem_u32(const void* p) {
    uint32_t a;
    asm("{ .reg .u64 t; cvta.to.shared.u64 t, %1; cvt.u32.u64 %0, t; }" : "=r"(a) : "l"(p));
    return a;
}
__device__ __forceinline__ uint32_t pk_bf2(__nv_bfloat16 a, __nv_bfloat16 b) {
    __nv_bfloat162 t(a, b);
    return *reinterpret_cast<uint32_t*>(&t);
}
__device__ __forceinline__ void split2(float x, float y, uint32_t& hi, uint32_t& lo) {
    __nv_bfloat16 xh = __float2bfloat16(x), yh = __float2bfloat16(y);
    __nv_bfloat16 xl = __float2bfloat16(x - __bfloat162float(xh));
    __nv_bfloat16 yl = __float2bfloat16(y - __bfloat162float(yh));
    hi = pk_bf2(xh, yh);
    lo = pk_bf2(xl, yl);
}
__device__ __forceinline__ void ldsm4(uint32_t& r0, uint32_t& r1, uint32_t& r2, uint32_t& r3,
                                      uint32_t addr) {
    asm volatile("ldmatrix.sync.aligned.m8n8.x4.shared.b16 {%0,%1,%2,%3}, [%4];"
                 : "=r"(r0), "=r"(r1), "=r"(r2), "=r"(r3) : "r"(addr));
}
__device__ __forceinline__ void ldsm4t(uint32_t& r0, uint32_t& r1, uint32_t& r2, uint32_t& r3,
                                       uint32_t addr) {
    asm volatile("ldmatrix.sync.aligned.m8n8.x4.trans.shared.b16 {%0,%1,%2,%3}, [%4];"
                 : "=r"(r0), "=r"(r1), "=r"(r2), "=r"(r3) : "r"(addr));
}
__device__ __forceinline__ void mma16816(float* c, uint32_t a0, uint32_t a1, uint32_t a2,
                                         uint32_t a3, uint32_t b0, uint32_t b1) {
    asm volatile(
        "mma.sync.aligned.m16n8k16.row.col.f32.bf16.bf16.f32 "
        "{%0,%1,%2,%3}, {%4,%5,%6,%7}, {%8,%9}, {%0,%1,%2,%3};"
        : "+f"(c[0]), "+f"(c[1]), "+f"(c[2]), "+f"(c[3])
        : "r"(a0), "r"(a1), "r"(a2), "r"(a3), "r"(b0), "r"(b1));
}

// ===========================================================================
// prep: fp32 -> bf16 hi/lo split (vectorized, grid-stride free)
// ===========================================================================
__global__ void __launch_bounds__(256) split_f32(
    const float* __restrict__ src, __nv_bfloat16* __restrict__ hi,
    __nv_bfloat16* __restrict__ lo, int n4)
{
    int i = blockIdx.x * blockDim.x + threadIdx.x;
    if (i >= n4) return;
    float4 v = ((const float4*)src)[i];
    uint32_t h0, l0, h1, l1;
    split2(v.x, v.y, h0, l0);
    split2(v.z, v.w, h1, l1);
    ((uint2*)hi)[i] = make_uint2(h0, h1);
    ((uint2*)lo)[i] = make_uint2(l0, l1);
}

// ===========================================================================
// bf16 3-term GEMM: C[z][M,N] = A[M,K] * B[z][K,N] + bias (+res)
// tile 128x128x32, 8 warps (4M x 2N), warp tile 32x64
// ===========================================================================
#define ASTR 80          // bytes per A smem row (32 bf16 data + pad) : 5 granules
#define BSTR 272         // bytes per B smem row (128 bf16 data + pad): 17 granules
#define SA_HI 0
#define SA_LO 10240
#define SB_HI 20480
#define SB_LO 29184
#define GEMM_SMEM 37888

template<bool RES>
__global__ void __launch_bounds__(256, 2) gemm_bf16(
    const __nv_bfloat16* __restrict__ Ahi, const __nv_bfloat16* __restrict__ Alo,
    const __nv_bfloat16* __restrict__ Bhi, const __nv_bfloat16* __restrict__ Blo,
    const float* __restrict__ bias, const float* __restrict__ res,
    float* __restrict__ C, int M, int N, int K)
{
    __shared__ char sm[GEMM_SMEM];
    const int z  = blockIdx.z;
    const int n0 = blockIdx.x * 128;
    const int m0 = blockIdx.y * 128;
    const int tid  = threadIdx.x;
    const int wid  = tid >> 5;
    const int lane = tid & 31;
    const int wm = wid & 3;          // M warp coord (4)
    const int wn = wid >> 2;         // N warp coord (2)

    const __nv_bfloat16* Bhz = Bhi + (size_t)z * K * N;
    const __nv_bfloat16* Blz = Blo + (size_t)z * K * N;

    float acc[2][8][4];
#pragma unroll
    for (int i = 0; i < 2; i++)
#pragma unroll
        for (int j = 0; j < 8; j++)
#pragma unroll
            for (int e = 0; e < 4; e++) acc[i][j][e] = 0.f;

    const uint32_t smb = smem_u32(sm);
    const int lr = lane & 15;
    const int lc = lane >> 4;
    const uint32_t aAddr = smb + SA_HI + (uint32_t)(wm * 32 + lr) * ASTR + lc * 16;
    const uint32_t bAddr = smb + SB_HI + (uint32_t)lr * BSTR + wn * 128 + lc * 16;

    for (int k0 = 0; k0 < K; k0 += 32) {
        // ---- load A tile 128x32, B tile 32x128 (hi+lo), 16B chunks ----
#pragma unroll
        for (int l = 0; l < 2; l++) {
            int f  = tid + l * 256;
            int am = f >> 2;
            int ak = (f & 3) << 3;
            size_t ga = (size_t)(m0 + am) * K + k0 + ak;
            *(uint4*)(sm + SA_HI + am * ASTR + ak * 2) = *(const uint4*)(Ahi + ga);
            *(uint4*)(sm + SA_LO + am * ASTR + ak * 2) = *(const uint4*)(Alo + ga);
            int bk = f >> 4;
            int bn = (f & 15) << 3;
            size_t gb = (size_t)(k0 + bk) * N + n0 + bn;
            *(uint4*)(sm + SB_HI + bk * BSTR + bn * 2) = *(const uint4*)(Bhz + gb);
            *(uint4*)(sm + SB_LO + bk * BSTR + bn * 2) = *(const uint4*)(Blz + gb);
        }
        __syncthreads();

#pragma unroll
        for (int ks = 0; ks < 2; ++ks) {
            uint32_t bh[4][4], bl[4][4];
#pragma unroll
            for (int g = 0; g < 4; ++g) {
                uint32_t base = bAddr + ks * (16 * BSTR) + g * 32;
                ldsm4t(bh[g][0], bh[g][1], bh[g][2], bh[g][3], base);
                ldsm4t(bl[g][0], bl[g][1], bl[g][2], bl[g][3], base + (SB_LO - SB_HI));
            }
#pragma unroll
            for (int mt = 0; mt < 2; ++mt) {
                uint32_t abase = aAddr + mt * (16 * ASTR) + ks * 32;
                uint32_t ah0, ah1, ah2, ah3, al0, al1, al2, al3;
                ldsm4(ah0, ah1, ah2, ah3, abase);
                ldsm4(al0, al1, al2, al3, abase + (SA_LO - SA_HI));
#pragma unroll
                for (int g = 0; g < 4; ++g) {
                    float* c0 = acc[mt][2 * g];
                    float* c1 = acc[mt][2 * g + 1];
                    mma16816(c0, ah0, ah1, ah2, ah3, bh[g][0], bh[g][1]);
                    mma16816(c0, ah0, ah1, ah2, ah3, bl[g][0], bl[g][1]);
                    mma16816(c0, al0, al1, al2, al3, bh[g][0], bh[g][1]);
                    mma16816(c1, ah0, ah1, ah2, ah3, bh[g][2], bh[g][3]);
                    mma16816(c1, ah0, ah1, ah2, ah3, bl[g][2], bl[g][3]);
                    mma16816(c1, al0, al1, al2, al3, bh[g][2], bh[g][3]);
                }
            }
        }
        __syncthreads();
    }

    // ---- epilogue: bias (+res), fp32 out ----
    float* Cz = C + (size_t)z * M * N;
#pragma unroll
    for (int mt = 0; mt < 2; ++mt) {
        int r1 = m0 + wm * 32 + mt * 16 + (lane >> 2);
        int r2 = r1 + 8;
        float b1 = bias[r1];
        float b2 = bias[r2];
#pragma unroll
        for (int g = 0; g < 8; ++g) {
            int col = n0 + wn * 64 + g * 8 + ((lane & 3) << 1);
            float2 w1 = make_float2(acc[mt][g][0] + b1, acc[mt][g][1] + b1);
            float2 w2 = make_float2(acc[mt][g][2] + b2, acc[mt][g][3] + b2);
            if (RES) {
                float2 q1 = *(const float2*)(res + (size_t)z * M * N + (size_t)r1 * N + col);
                float2 q2 = *(const float2*)(res + (size_t)z * M * N + (size_t)r2 * N + col);
                w1.x += q1.x; w1.y += q1.y;
                w2.x += q2.x; w2.y += q2.y;
            }
            *(float2*)(Cz + (size_t)r1 * N + col) = w1;
            *(float2*)(Cz + (size_t)r2 * N + col) = w2;
        }
    }
}

// ===========================================================================
// Attention via mma.sync bf16 (3-term hi/lo) — verified in R3
// ===========================================================================
#define BT2 128
#define BS2 64
#define NIT (T_LEN / BS2)

#define SM_QHI 0
#define SM_QLO 18432
#define SM_KHI 36864
#define SM_KLO 46080
#define SM_VHI 55296
#define SM_VLO 64512
#define SM_OST 36864
#define ATTN_SMEM 73728

__global__ void __launch_bounds__(256, 2) attn_mma()
{
    extern __shared__ char sm[];
    const int tid  = threadIdx.x;
    const int wid  = tid >> 5;
    const int lane = tid & 31;
    const int t0 = blockIdx.x * BT2;
    const int h  = blockIdx.y;
    const int b  = blockIdx.z;

    const float* qg = g_qkv + ((size_t)b * 3 * CC + h * HD) * T_LEN;
    const float* kg = qg + (size_t)CC * T_LEN;
    const float* vg = kg + (size_t)CC * T_LEN;

    const float scale = 0.044194173824159216f;   // 512^-0.5

#pragma unroll
    for (int l = 0; l < 8; ++l) {
        int f  = tid + l * 256;
        int d  = f >> 5;
        int t4 = (f & 31) << 2;
        float4 v = *(const float4*)(qg + (size_t)d * T_LEN + t0 + t4);
        float vv[4] = {v.x * scale, v.y * scale, v.z * scale, v.w * scale};
#pragma unroll
        for (int e = 0; e < 4; ++e) {
            __nv_bfloat16 hi = __float2bfloat16(vv[e]);
            __nv_bfloat16 lo = __float2bfloat16(vv[e] - __bfloat162float(hi));
            *(__nv_bfloat16*)(sm + SM_QHI + (size_t)(t4 + e) * 144 + d * 2) = hi;
            *(__nv_bfloat16*)(sm + SM_QLO + (size_t)(t4 + e) * 144 + d * 2) = lo;
        }
    }

    float oacc[32];
#pragma unroll
    for (int i = 0; i < 32; ++i) oacc[i] = 0.f;
    float m_r1 = -INFINITY, m_r2 = -INFINITY, l_r1 = 0.f, l_r2 = 0.f;

    const uint32_t smb = smem_u32(sm);
    const int lr = lane & 15;
    const int lc = lane >> 4;
    const uint32_t qa_hi = smb + SM_QHI + (uint32_t)(wid * 16 + lr) * 144 + lc * 16;
    const uint32_t qa_lo = qa_hi + (SM_QLO - SM_QHI);
    const uint32_t kb_hi = smb + SM_KHI + (uint32_t)lr * 144 + lc * 16;
    const uint32_t kb_lo = kb_hi + (SM_KLO - SM_KHI);
    const uint32_t vb_hi = smb + SM_VHI + (uint32_t)lr * 144 + lc * 16;
    const uint32_t vb_lo = vb_hi + (SM_VLO - SM_VHI);

    __syncthreads();

    for (int it = 0; it < NIT; ++it) {
        const int s0 = it * BS2;

#pragma unroll
        for (int l = 0; l < 4; ++l) {
            int f  = tid + l * 256;
            int d  = f >> 4;
            int s4 = (f & 15) << 2;
            float4 v = *(const float4*)(kg + (size_t)d * T_LEN + s0 + s4);
            uint32_t h0, l0, h1, l1;
            split2(v.x, v.y, h0, l0);
            split2(v.z, v.w, h1, l1);
            *(uint2*)(sm + SM_KHI + (size_t)d * 144 + s4 * 2) = make_uint2(h0, h1);
            *(uint2*)(sm + SM_KLO + (size_t)d * 144 + s4 * 2) = make_uint2(l0, l1);
        }
#pragma unroll
        for (int l = 0; l < 4; ++l) {
            int f  = tid + l * 256;
            int d  = f >> 4;
            int s4 = (f & 15) << 2;
            float4 v = *(const float4*)(vg + (size_t)d * T_LEN + s0 + s4);
            float vv[4] = {v.x, v.y, v.z, v.w};
#pragma unroll
            for (int e = 0; e < 4; ++e) {
                __nv_bfloat16 hi = __float2bfloat16(vv[e]);
                __nv_bfloat16 lo = __float2bfloat16(vv[e] - __bfloat162float(hi));
                *(__nv_bfloat16*)(sm + SM_VHI + (size_t)(s4 + e) * 144 + d * 2) = hi;
                *(__nv_bfloat16*)(sm + SM_VLO + (size_t)(s4 + e) * 144 + d * 2) = lo;
            }
        }
        __syncthreads();

        float sacc[32];
#pragma unroll
        for (int i = 0; i < 32; ++i) sacc[i] = 0.f;
#pragma unroll
        for (int ks = 0; ks < 4; ++ks) {
            uint32_t qh0, qh1, qh2, qh3, ql0, ql1, ql2, ql3;
            ldsm4(qh0, qh1, qh2, qh3, qa_hi + ks * 32);
            ldsm4(ql0, ql1, ql2, ql3, qa_lo + ks * 32);
#pragma unroll
            for (int np = 0; np < 4; ++np) {
                uint32_t bh0, bh1, bh2, bh3, bl0, bl1, bl2, bl3;
                ldsm4t(bh0, bh1, bh2, bh3, kb_hi + ks * 2304 + np * 32);
                ldsm4t(bl0, bl1, bl2, bl3, kb_lo + ks * 2304 + np * 32);
                float* c0 = &sacc[np * 8];
                float* c1 = &sacc[np * 8 + 4];
                mma16816(c0, qh0, qh1, qh2, qh3, bh0, bh1);
                mma16816(c0, qh0, qh1, qh2, qh3, bl0, bl1);
                mma16816(c0, ql0, ql1, ql2, ql3, bh0, bh1);
                mma16816(c1, qh0, qh1, qh2, qh3, bh2, bh3);
                mma16816(c1, qh0, qh1, qh2, qh3, bl2, bl3);
                mma16816(c1, ql0, ql1, ql2, ql3, bh2, bh3);
            }
        }

        float nm1 = -INFINITY, nm2 = -INFINITY;
#pragma unroll
        for (int j = 0; j < 8; ++j) {
            nm1 = fmaxf(nm1, fmaxf(sacc[4 * j],     sacc[4 * j + 1]));
            nm2 = fmaxf(nm2, fmaxf(sacc[4 * j + 2], sacc[4 * j + 3]));
        }
        nm1 = fmaxf(nm1, __shfl_xor_sync(0xffffffffu, nm1, 1));
        nm1 = fmaxf(nm1, __shfl_xor_sync(0xffffffffu, nm1, 2));
        nm2 = fmaxf(nm2, __shfl_xor_sync(0xffffffffu, nm2, 1));
        nm2 = fmaxf(nm2, __shfl_xor_sync(0xffffffffu, nm2, 2));
        const float mn1 = fmaxf(m_r1, nm1);
        const float mn2 = fmaxf(m_r2, nm2);
        const float a1 = __expf(m_r1 - mn1);
        const float a2 = __expf(m_r2 - mn2);
        float s1 = 0.f, s2 = 0.f;
#pragma unroll
        for (int j = 0; j < 8; ++j) {
            float e0 = __expf(sacc[4 * j]     - mn1);
            float e1 = __expf(sacc[4 * j + 1] - mn1);
            float e2 = __expf(sacc[4 * j + 2] - mn2);
            float e3 = __expf(sacc[4 * j + 3] - mn2);
            sacc[4 * j] = e0; sacc[4 * j + 1] = e1; sacc[4 * j + 2] = e2; sacc[4 * j + 3] = e3;
            s1 += e0 + e1;
            s2 += e2 + e3;
        }
        s1 += __shfl_xor_sync(0xffffffffu, s1, 1);
        s1 += __shfl_xor_sync(0xffffffffu, s1, 2);
        s2 += __shfl_xor_sync(0xffffffffu, s2, 1);
        s2 += __shfl_xor_sync(0xffffffffu, s2, 2);
        l_r1 = l_r1 * a1 + s1;
        l_r2 = l_r2 * a2 + s2;
        m_r1 = mn1;
        m_r2 = mn2;
#pragma unroll
        for (int j = 0; j < 8; ++j) {
            oacc[4 * j]     *= a1;
            oacc[4 * j + 1] *= a1;
            oacc[4 * j + 2] *= a2;
            oacc[4 * j + 3] *= a2;
        }

#pragma unroll
        for (int ks = 0; ks < 4; ++ks) {
            const float* sA = &sacc[8 * ks];
            uint32_t ph0, ph1, ph2, ph3, pl0, pl1, pl2, pl3;
            split2(sA[0], sA[1], ph0, pl0);
            split2(sA[2], sA[3], ph1, pl1);
            split2(sA[4], sA[5], ph2, pl2);
            split2(sA[6], sA[7], ph3, pl3);
#pragma unroll
            for (int np = 0; np < 4; ++np) {
                uint32_t bh0, bh1, bh2, bh3, bl0, bl1, bl2, bl3;
                ldsm4t(bh0, bh1, bh2, bh3, vb_hi + ks * 2304 + np * 32);
                ldsm4t(bl0, bl1, bl2, bl3, vb_lo + ks * 2304 + np * 32);
                float* c0 = &oacc[np * 8];
                float* c1 = &oacc[np * 8 + 4];
                mma16816(c0, ph0, ph1, ph2, ph3, bh0, bh1);
                mma16816(c0, ph0, ph1, ph2, ph3, bl0, bl1);
                mma16816(c0, pl0, pl1, pl2, pl3, bh0, bh1);
                mma16816(c1, ph0, ph1, ph2, ph3, bh2, bh3);
                mma16816(c1, ph0, ph1, ph2, ph3, bl2, bl3);
                mma16816(c1, pl0, pl1, pl2, pl3, bh2, bh3);
            }
        }
        __syncthreads();
    }

    {
        float* so = (float*)(sm + SM_OST);
        const float i1 = 1.f / l_r1;
        const float i2 = 1.f / l_r2;
        const int r  = lane >> 2;
        const int tw = wid * 16;
#pragma unroll
        for (int j = 0; j < 8; ++j) {
            int d0 = 8 * j + ((lane & 3) << 1);
            so[(size_t)d0 * 128 + tw + r]           = oacc[4 * j]     * i1;
            so[(size_t)(d0 + 1) * 128 + tw + r]     = oacc[4 * j + 1] * i1;
            so[(size_t)d0 * 128 + tw + r + 8]       = oacc[4 * j + 2] * i2;
            so[(size_t)(d0 + 1) * 128 + tw + r + 8] = oacc[4 * j + 3] * i2;
        }
        __syncthreads();
        float* og = g_att + ((size_t)b * CC + h * HD) * T_LEN;
#pragma unroll
        for (int l = 0; l < 8; ++l) {
            int f  = tid + l * 256;
            int c  = f >> 5;
            int t4 = (f & 31) << 2;
            *(float4*)(og + (size_t)c * T_LEN + t0 + t4) = *(float4*)&so[(size_t)c * 128 + t4];
        }
    }
}

// ===========================================================================
extern "C" void kernel_launch(void* const* d_in, const int* in_sizes, int n_in,
                              void* d_out, int out_size)
{
    const float* x      = (const float*)d_in[0];
    const float* qkv_w  = (const float*)d_in[1];
    const float* qkv_b  = (const float*)d_in[2];
    const float* proj_w = (const float*)d_in[3];
    const float* proj_b = (const float*)d_in[4];
    float* out = (float*)d_out;

    float *qkv_ptr = nullptr, *att_ptr = nullptr;
    __nv_bfloat16 *whi, *wlo, *xhi, *xlo;
    cudaGetSymbolAddress((void**)&qkv_ptr, g_qkv);
    cudaGetSymbolAddress((void**)&att_ptr, g_att);
    cudaGetSymbolAddress((void**)&whi, g_whi);
    cudaGetSymbolAddress((void**)&wlo, g_wlo);
    cudaGetSymbolAddress((void**)&xhi, g_xhi);
    cudaGetSymbolAddress((void**)&xlo, g_xlo);
    cudaFuncSetAttribute((const void*)attn_mma,
                         cudaFuncAttributeMaxDynamicSharedMemorySize, ATTN_SMEM);

    const int QW4 = (3 * CC * CC) / 4;
    const int PW4 = (CC * CC) / 4;
    const int X4  = (int)(X_ELEMS / 4);
    const int PW_OFF = 3 * CC * CC;

    // prep: hi/lo splits
    split_f32<<<(QW4 + 255) / 256, 256>>>(qkv_w, whi, wlo, QW4);
    split_f32<<<(PW4 + 255) / 256, 256>>>(proj_w, whi + PW_OFF, wlo + PW_OFF, PW4);
    split_f32<<<(X4 + 255) / 256, 256>>>(x, xhi, xlo, X4);

    // 1) qkv = W_qkv @ x + b   (bf16 3-term tensor GEMM)
    gemm_bf16<false><<<dim3(T_LEN / 128, (3 * CC) / 128, BATCH), 256>>>(
        whi, wlo, xhi, xlo, qkv_b, nullptr, qkv_ptr, 3 * CC, T_LEN, CC);

    // 2) attention
    attn_mma<<<dim3(T_LEN / BT2, NH, BATCH), 256, ATTN_SMEM>>>();

    // 3) split attention output, then out = x + W_proj @ att + b
    split_f32<<<(X4 + 255) / 256, 256>>>(att_ptr, xhi, xlo, X4);
    gemm_bf16<true><<<dim3(T_LEN / 128, CC / 128, BATCH), 256>>>(
        whi + PW_OFF, wlo + PW_OFF, xhi, xlo, proj_b, x, out, CC, T_LEN, CC);
}

// round 5
// speedup vs baseline: 2.8131x; 1.2822x over previous
#include <cuda_runtime.h>
#include <cuda_bf16.h>
#include <math.h>
#include <stdint.h>

#define CC     512
#define T_LEN  2048
#define BATCH  4
#define NH     8
#define HD     64

// Scratch (allocation-free rule: __device__ globals)
#define W_ELEMS (3 * CC * CC + CC * CC)             // qkv_w then proj_w
#define X_ELEMS ((size_t)BATCH * CC * T_LEN)
#define QKV_ELEMS ((size_t)BATCH * 3 * CC * T_LEN)
__device__ __nv_bfloat16 g_whi[W_ELEMS];
__device__ __nv_bfloat16 g_wlo[W_ELEMS];
__device__ __nv_bfloat16 g_xhi[X_ELEMS];            // x split, later attn output split
__device__ __nv_bfloat16 g_xlo[X_ELEMS];
__device__ __nv_bfloat16 g_qkvhi[QKV_ELEMS];        // QKV GEMM output (hi/lo)
__device__ __nv_bfloat16 g_qkvlo[QKV_ELEMS];

// ===========================================================================
// helpers
// ===========================================================================
__device__ __forceinline__ uint32_t smem_u32(const void* p) {
    uint32_t a;
    asm("{ .reg .u64 t; cvta.to.shared.u64 t, %1; cvt.u32.u64 %0, t; }" : "=r"(a) : "l"(p));
    return a;
}
__device__ __forceinline__ uint32_t pk_bf2(__nv_bfloat16 a, __nv_bfloat16 b) {
    __nv_bfloat162 t(a, b);
    return *reinterpret_cast<uint32_t*>(&t);
}
__device__ __forceinline__ void split2(float x, float y, uint32_t& hi, uint32_t& lo) {
    __nv_bfloat16 xh = __float2bfloat16(x), yh = __float2bfloat16(y);
    __nv_bfloat16 xl = __float2bfloat16(x - __bfloat162float(xh));
    __nv_bfloat16 yl = __float2bfloat16(y - __bfloat162float(yh));
    hi = pk_bf2(xh, yh);
    lo = pk_bf2(xl, yl);
}
__device__ __forceinline__ void ldsm4(uint32_t& r0, uint32_t& r1, uint32_t& r2, uint32_t& r3,
                                      uint32_t addr) {
    asm volatile("ldmatrix.sync.aligned.m8n8.x4.shared.b16 {%0,%1,%2,%3}, [%4];"
                 : "=r"(r0), "=r"(r1), "=r"(r2), "=r"(r3) : "r"(addr));
}
__device__ __forceinline__ void ldsm4t(uint32_t& r0, uint32_t& r1, uint32_t& r2, uint32_t& r3,
                                       uint32_t addr) {
    asm volatile("ldmatrix.sync.aligned.m8n8.x4.trans.shared.b16 {%0,%1,%2,%3}, [%4];"
                 : "=r"(r0), "=r"(r1), "=r"(r2), "=r"(r3) : "r"(addr));
}
__device__ __forceinline__ void mma16816(float* c, uint32_t a0, uint32_t a1, uint32_t a2,
                                         uint32_t a3, uint32_t b0, uint32_t b1) {
    asm volatile(
        "mma.sync.aligned.m16n8k16.row.col.f32.bf16.bf16.f32 "
        "{%0,%1,%2,%3}, {%4,%5,%6,%7}, {%8,%9}, {%0,%1,%2,%3};"
        : "+f"(c[0]), "+f"(c[1]), "+f"(c[2]), "+f"(c[3])
        : "r"(a0), "r"(a1), "r"(a2), "r"(a3), "r"(b0), "r"(b1));
}

// ===========================================================================
// prep: fp32 -> bf16 hi/lo split
// ===========================================================================
__global__ void __launch_bounds__(256) split_f32(
    const float* __restrict__ src, __nv_bfloat16* __restrict__ hi,
    __nv_bfloat16* __restrict__ lo, int n4)
{
    int i = blockIdx.x * blockDim.x + threadIdx.x;
    if (i >= n4) return;
    float4 v = ((const float4*)src)[i];
    uint32_t h0, l0, h1, l1;
    split2(v.x, v.y, h0, l0);
    split2(v.z, v.w, h1, l1);
    ((uint2*)hi)[i] = make_uint2(h0, h1);
    ((uint2*)lo)[i] = make_uint2(l0, l1);
}

// ===========================================================================
// bf16 3-term GEMM, tile 128x128x32, 8 warps (4M x 2N)
// SPLITOUT: write bf16 hi/lo (no res); else fp32 + bias (+res)
// ===========================================================================
#define ASTR 80
#define BSTR 272
#define SA_HI 0
#define SA_LO 10240
#define SB_HI 20480
#define SB_LO 29184
#define GEMM_SMEM 37888

template<bool RES, bool SPLITOUT>
__global__ void __launch_bounds__(256, 2) gemm_bf16(
    const __nv_bfloat16* __restrict__ Ahi, const __nv_bfloat16* __restrict__ Alo,
    const __nv_bfloat16* __restrict__ Bhi, const __nv_bfloat16* __restrict__ Blo,
    const float* __restrict__ bias, const float* __restrict__ res,
    float* __restrict__ C, __nv_bfloat16* __restrict__ Chi, __nv_bfloat16* __restrict__ Clo,
    int M, int N, int K)
{
    __shared__ char sm[GEMM_SMEM];
    const int z  = blockIdx.z;
    const int n0 = blockIdx.x * 128;
    const int m0 = blockIdx.y * 128;
    const int tid  = threadIdx.x;
    const int wid  = tid >> 5;
    const int lane = tid & 31;
    const int wm = wid & 3;
    const int wn = wid >> 2;

    const __nv_bfloat16* Bhz = Bhi + (size_t)z * K * N;
    const __nv_bfloat16* Blz = Blo + (size_t)z * K * N;

    float acc[2][8][4];
#pragma unroll
    for (int i = 0; i < 2; i++)
#pragma unroll
        for (int j = 0; j < 8; j++)
#pragma unroll
            for (int e = 0; e < 4; e++) acc[i][j][e] = 0.f;

    const uint32_t smb = smem_u32(sm);
    const int lr = lane & 15;
    const int lc = lane >> 4;
    const uint32_t aAddr = smb + SA_HI + (uint32_t)(wm * 32 + lr) * ASTR + lc * 16;
    const uint32_t bAddr = smb + SB_HI + (uint32_t)lr * BSTR + wn * 128 + lc * 16;

    for (int k0 = 0; k0 < K; k0 += 32) {
#pragma unroll
        for (int l = 0; l < 2; l++) {
            int f  = tid + l * 256;
            int am = f >> 2;
            int ak = (f & 3) << 3;
            size_t ga = (size_t)(m0 + am) * K + k0 + ak;
            *(uint4*)(sm + SA_HI + am * ASTR + ak * 2) = *(const uint4*)(Ahi + ga);
            *(uint4*)(sm + SA_LO + am * ASTR + ak * 2) = *(const uint4*)(Alo + ga);
            int bk = f >> 4;
            int bn = (f & 15) << 3;
            size_t gb = (size_t)(k0 + bk) * N + n0 + bn;
            *(uint4*)(sm + SB_HI + bk * BSTR + bn * 2) = *(const uint4*)(Bhz + gb);
            *(uint4*)(sm + SB_LO + bk * BSTR + bn * 2) = *(const uint4*)(Blz + gb);
        }
        __syncthreads();

#pragma unroll
        for (int ks = 0; ks < 2; ++ks) {
            uint32_t bh[4][4], bl[4][4];
#pragma unroll
            for (int g = 0; g < 4; ++g) {
                uint32_t base = bAddr + ks * (16 * BSTR) + g * 32;
                ldsm4t(bh[g][0], bh[g][1], bh[g][2], bh[g][3], base);
                ldsm4t(bl[g][0], bl[g][1], bl[g][2], bl[g][3], base + (SB_LO - SB_HI));
            }
#pragma unroll
            for (int mt = 0; mt < 2; ++mt) {
                uint32_t abase = aAddr + mt * (16 * ASTR) + ks * 32;
                uint32_t ah0, ah1, ah2, ah3, al0, al1, al2, al3;
                ldsm4(ah0, ah1, ah2, ah3, abase);
                ldsm4(al0, al1, al2, al3, abase + (SA_LO - SA_HI));
#pragma unroll
                for (int g = 0; g < 4; ++g) {
                    float* c0 = acc[mt][2 * g];
                    float* c1 = acc[mt][2 * g + 1];
                    mma16816(c0, ah0, ah1, ah2, ah3, bh[g][0], bh[g][1]);
                    mma16816(c0, ah0, ah1, ah2, ah3, bl[g][0], bl[g][1]);
                    mma16816(c0, al0, al1, al2, al3, bh[g][0], bh[g][1]);
                    mma16816(c1, ah0, ah1, ah2, ah3, bh[g][2], bh[g][3]);
                    mma16816(c1, ah0, ah1, ah2, ah3, bl[g][2], bl[g][3]);
                    mma16816(c1, al0, al1, al2, al3, bh[g][2], bh[g][3]);
                }
            }
        }
        __syncthreads();
    }

#pragma unroll
    for (int mt = 0; mt < 2; ++mt) {
        int r1 = m0 + wm * 32 + mt * 16 + (lane >> 2);
        int r2 = r1 + 8;
        float b1 = bias[r1];
        float b2 = bias[r2];
#pragma unroll
        for (int g = 0; g < 8; ++g) {
            int col = n0 + wn * 64 + g * 8 + ((lane & 3) << 1);
            float2 w1 = make_float2(acc[mt][g][0] + b1, acc[mt][g][1] + b1);
            float2 w2 = make_float2(acc[mt][g][2] + b2, acc[mt][g][3] + b2);
            if (SPLITOUT) {
                __nv_bfloat16* ChZ = Chi + (size_t)z * M * N;
                __nv_bfloat16* ClZ = Clo + (size_t)z * M * N;
                uint32_t h, l;
                split2(w1.x, w1.y, h, l);
                *(uint32_t*)(ChZ + (size_t)r1 * N + col) = h;
                *(uint32_t*)(ClZ + (size_t)r1 * N + col) = l;
                split2(w2.x, w2.y, h, l);
                *(uint32_t*)(ChZ + (size_t)r2 * N + col) = h;
                *(uint32_t*)(ClZ + (size_t)r2 * N + col) = l;
            } else {
                float* Cz = C + (size_t)z * M * N;
                if (RES) {
                    float2 q1 = *(const float2*)(res + (size_t)z * M * N + (size_t)r1 * N + col);
                    float2 q2 = *(const float2*)(res + (size_t)z * M * N + (size_t)r2 * N + col);
                    w1.x += q1.x; w1.y += q1.y;
                    w2.x += q2.x; w2.y += q2.y;
                }
                *(float2*)(Cz + (size_t)r1 * N + col) = w1;
                *(float2*)(Cz + (size_t)r2 * N + col) = w2;
            }
        }
    }
}

// ===========================================================================
// Attention: mma.sync bf16 3-term. All operands pre-split bf16, natural layout.
// Q [d][t] (trans-ldsm A), K [d][s] (trans-ldsm B), V [d][s] (non-trans ldsm B).
// ===========================================================================
#define BT2 128
#define BS2 64
#define NIT (T_LEN / BS2)

#define QSTR 272
#define KSTR 144
#define SM_QHI 0
#define SM_QLO 17408
#define SM_KHI 34816
#define SM_KLO 44032
#define SM_VHI 53248
#define SM_VLO 62464
#define SM_OST 34816        // fp32 staging reuses K/V region (needs 32768)
#define ATTN_SMEM 71680

__global__ void __launch_bounds__(256, 2) attn_mma()
{
    extern __shared__ char sm[];
    const int tid  = threadIdx.x;
    const int wid  = tid >> 5;
    const int lane = tid & 31;
    const int t0 = blockIdx.x * BT2;
    const int h  = blockIdx.y;
    const int b  = blockIdx.z;

    const size_t qoff = ((size_t)b * 3 * CC + h * HD) * T_LEN;
    const __nv_bfloat16* qhi = g_qkvhi + qoff;
    const __nv_bfloat16* qlo = g_qkvlo + qoff;
    const __nv_bfloat16* khi = qhi + (size_t)CC * T_LEN;
    const __nv_bfloat16* klo = qlo + (size_t)CC * T_LEN;
    const __nv_bfloat16* vhi = khi + (size_t)CC * T_LEN;
    const __nv_bfloat16* vlo = klo + (size_t)CC * T_LEN;

    // ---- Q tile [d=64][t=128]: pure copies ----
#pragma unroll
    for (int l = 0; l < 4; ++l) {
        int f = tid + l * 256;
        int d = f >> 4;
        int c = f & 15;                       // 16B chunk (8 bf16)
        size_t g = (size_t)d * T_LEN + t0 + c * 8;
        *(uint4*)(sm + SM_QHI + d * QSTR + c * 16) = *(const uint4*)(qhi + g);
        *(uint4*)(sm + SM_QLO + d * QSTR + c * 16) = *(const uint4*)(qlo + g);
    }

    float oacc[32];
#pragma unroll
    for (int i = 0; i < 32; ++i) oacc[i] = 0.f;
    float m_r1 = -INFINITY, m_r2 = -INFINITY, l_r1 = 0.f, l_r2 = 0.f;

    const uint32_t smb = smem_u32(sm);
    // A-frag (Q) trans-ldsm addressing: rows=d, cols=t
    const int q8 = lane & 7;
    const int qh2 = (lane >> 3) & 1;          // t half (16B)
    const int qd2 = lane >> 4;                // d half (+8 rows)
    const uint32_t qa_hi = smb + SM_QHI + (uint32_t)(q8 + 8 * qd2) * QSTR + wid * 32 + qh2 * 16;
    const uint32_t qa_lo = qa_hi + (SM_QLO - SM_QHI);
    // B-frag (K) trans-ldsm addressing: rows=d(=k), cols=s
    const int lr = lane & 15;
    const int lc = lane >> 4;
    const uint32_t kb_hi = smb + SM_KHI + (uint32_t)lr * KSTR + lc * 16;
    const uint32_t kb_lo = kb_hi + (SM_KLO - SM_KHI);
    // B-frag (V) non-trans ldsm addressing: rows=d(=n), cols=s(=k)
    const int v8 = lane & 7;
    const int vh2 = (lane >> 3) & 1;          // s half (16B)
    const int vd2 = lane >> 4;                // d half (+8 rows)
    const uint32_t vb_hi = smb + SM_VHI + (uint32_t)(v8 + 8 * vd2) * KSTR + vh2 * 16;
    const uint32_t vb_lo = vb_hi + (SM_VLO - SM_VHI);

    const float scale = 0.044194173824159216f;   // 512^-0.5

    __syncthreads();

    for (int it = 0; it < NIT; ++it) {
        const int s0 = it * BS2;

        // ---- K,V tiles [d=64][s=64]: pure copies ----
#pragma unroll
        for (int l = 0; l < 2; ++l) {
            int f = tid + l * 256;
            int d = f >> 3;
            int c = f & 7;
            size_t g = (size_t)d * T_LEN + s0 + c * 8;
            *(uint4*)(sm + SM_KHI + d * KSTR + c * 16) = *(const uint4*)(khi + g);
            *(uint4*)(sm + SM_KLO + d * KSTR + c * 16) = *(const uint4*)(klo + g);
            *(uint4*)(sm + SM_VHI + d * KSTR + c * 16) = *(const uint4*)(vhi + g);
            *(uint4*)(sm + SM_VLO + d * KSTR + c * 16) = *(const uint4*)(vlo + g);
        }
        __syncthreads();

        // ---- S = Q K^T ----
        float sacc[32];
#pragma unroll
        for (int i = 0; i < 32; ++i) sacc[i] = 0.f;
#pragma unroll
        for (int ks = 0; ks < 4; ++ks) {
            uint32_t qh0, qh1, qh2r, qh3, ql0, ql1, ql2, ql3;
            ldsm4t(qh0, qh1, qh2r, qh3, qa_hi + ks * (16 * QSTR));
            ldsm4t(ql0, ql1, ql2, ql3, qa_lo + ks * (16 * QSTR));
#pragma unroll
            for (int np = 0; np < 4; ++np) {
                uint32_t bh0, bh1, bh2, bh3, bl0, bl1, bl2, bl3;
                ldsm4t(bh0, bh1, bh2, bh3, kb_hi + ks * (16 * KSTR) + np * 32);
                ldsm4t(bl0, bl1, bl2, bl3, kb_lo + ks * (16 * KSTR) + np * 32);
                float* c0 = &sacc[np * 8];
                float* c1 = &sacc[np * 8 + 4];
                mma16816(c0, qh0, qh1, qh2r, qh3, bh0, bh1);
                mma16816(c0, qh0, qh1, qh2r, qh3, bl0, bl1);
                mma16816(c0, ql0, ql1, ql2, ql3, bh0, bh1);
                mma16816(c1, qh0, qh1, qh2r, qh3, bh2, bh3);
                mma16816(c1, qh0, qh1, qh2r, qh3, bl2, bl3);
                mma16816(c1, ql0, ql1, ql2, ql3, bh2, bh3);
            }
        }

        // ---- scale + online softmax ----
#pragma unroll
        for (int i = 0; i < 32; ++i) sacc[i] *= scale;
        float nm1 = -INFINITY, nm2 = -INFINITY;
#pragma unroll
        for (int j = 0; j < 8; ++j) {
            nm1 = fmaxf(nm1, fmaxf(sacc[4 * j],     sacc[4 * j + 1]));
            nm2 = fmaxf(nm2, fmaxf(sacc[4 * j + 2], sacc[4 * j + 3]));
        }
        nm1 = fmaxf(nm1, __shfl_xor_sync(0xffffffffu, nm1, 1));
        nm1 = fmaxf(nm1, __shfl_xor_sync(0xffffffffu, nm1, 2));
        nm2 = fmaxf(nm2, __shfl_xor_sync(0xffffffffu, nm2, 1));
        nm2 = fmaxf(nm2, __shfl_xor_sync(0xffffffffu, nm2, 2));
        const float mn1 = fmaxf(m_r1, nm1);
        const float mn2 = fmaxf(m_r2, nm2);
        const float a1 = __expf(m_r1 - mn1);
        const float a2 = __expf(m_r2 - mn2);
        float s1 = 0.f, s2 = 0.f;
#pragma unroll
        for (int j = 0; j < 8; ++j) {
            float e0 = __expf(sacc[4 * j]     - mn1);
            float e1 = __expf(sacc[4 * j + 1] - mn1);
            float e2 = __expf(sacc[4 * j + 2] - mn2);
            float e3 = __expf(sacc[4 * j + 3] - mn2);
            sacc[4 * j] = e0; sacc[4 * j + 1] = e1; sacc[4 * j + 2] = e2; sacc[4 * j + 3] = e3;
            s1 += e0 + e1;
            s2 += e2 + e3;
        }
        s1 += __shfl_xor_sync(0xffffffffu, s1, 1);
        s1 += __shfl_xor_sync(0xffffffffu, s1, 2);
        s2 += __shfl_xor_sync(0xffffffffu, s2, 1);
        s2 += __shfl_xor_sync(0xffffffffu, s2, 2);
        l_r1 = l_r1 * a1 + s1;
        l_r2 = l_r2 * a2 + s2;
        m_r1 = mn1;
        m_r2 = mn2;
#pragma unroll
        for (int j = 0; j < 8; ++j) {
            oacc[4 * j]     *= a1;
            oacc[4 * j + 1] *= a1;
            oacc[4 * j + 2] *= a2;
            oacc[4 * j + 3] *= a2;
        }

        // ---- O += P V^T ----
#pragma unroll
        for (int ks = 0; ks < 4; ++ks) {
            const float* sA = &sacc[8 * ks];
            uint32_t ph0, ph1, ph2, ph3, pl0, pl1, pl2, pl3;
            split2(sA[0], sA[1], ph0, pl0);
            split2(sA[2], sA[3], ph1, pl1);
            split2(sA[4], sA[5], ph2, pl2);
            split2(sA[6], sA[7], ph3, pl3);
#pragma unroll
            for (int np = 0; np < 4; ++np) {
                uint32_t bh0, bh1, bh2, bh3, bl0, bl1, bl2, bl3;
                uint32_t base = vb_hi + np * (16 * KSTR) + ks * 32;
                ldsm4(bh0, bh1, bh2, bh3, base);
                ldsm4(bl0, bl1, bl2, bl3, base + (SM_VLO - SM_VHI));
                float* c0 = &oacc[np * 8];
                float* c1 = &oacc[np * 8 + 4];
                mma16816(c0, ph0, ph1, ph2, ph3, bh0, bh1);
                mma16816(c0, ph0, ph1, ph2, ph3, bl0, bl1);
                mma16816(c0, pl0, pl1, pl2, pl3, bh0, bh1);
                mma16816(c1, ph0, ph1, ph2, ph3, bh2, bh3);
                mma16816(c1, ph0, ph1, ph2, ph3, bl2, bl3);
                mma16816(c1, pl0, pl1, pl2, pl3, bh2, bh3);
            }
        }
        __syncthreads();
    }

    // ---- epilogue: normalize, stage [d][t] fp32, write bf16 hi/lo split ----
    {
        float* so = (float*)(sm + SM_OST);
        const float i1 = 1.f / l_r1;
        const float i2 = 1.f / l_r2;
        const int r  = lane >> 2;
        const int tw = wid * 16;
#pragma unroll
        for (int j = 0; j < 8; ++j) {
            int d0 = 8 * j + ((lane & 3) << 1);
            so[(size_t)d0 * 128 + tw + r]           = oacc[4 * j]     * i1;
            so[(size_t)(d0 + 1) * 128 + tw + r]     = oacc[4 * j + 1] * i1;
            so[(size_t)d0 * 128 + tw + r + 8]       = oacc[4 * j + 2] * i2;
            so[(size_t)(d0 + 1) * 128 + tw + r + 8] = oacc[4 * j + 3] * i2;
        }
        __syncthreads();
        const size_t obase = ((size_t)b * CC + h * HD) * T_LEN;
#pragma unroll
        for (int l = 0; l < 8; ++l) {
            int f  = tid + l * 256;
            int c  = f >> 5;
            int t4 = (f & 31) << 2;
            float4 v = *(float4*)&so[(size_t)c * 128 + t4];
            uint32_t h0, l0, h1, l1;
            split2(v.x, v.y, h0, l0);
            split2(v.z, v.w, h1, l1);
            size_t g = obase + (size_t)c * T_LEN + t0 + t4;
            *(uint2*)(g_xhi + g) = make_uint2(h0, h1);
            *(uint2*)(g_xlo + g) = make_uint2(l0, l1);
        }
    }
}

// ===========================================================================
extern "C" void kernel_launch(void* const* d_in, const int* in_sizes, int n_in,
                              void* d_out, int out_size)
{
    const float* x      = (const float*)d_in[0];
    const float* qkv_w  = (const float*)d_in[1];
    const float* qkv_b  = (const float*)d_in[2];
    const float* proj_w = (const float*)d_in[3];
    const float* proj_b = (const float*)d_in[4];
    float* out = (float*)d_out;

    __nv_bfloat16 *whi, *wlo, *xhi, *xlo, *qkvhi, *qkvlo;
    cudaGetSymbolAddress((void**)&whi, g_whi);
    cudaGetSymbolAddress((void**)&wlo, g_wlo);
    cudaGetSymbolAddress((void**)&xhi, g_xhi);
    cudaGetSymbolAddress((void**)&xlo, g_xlo);
    cudaGetSymbolAddress((void**)&qkvhi, g_qkvhi);
    cudaGetSymbolAddress((void**)&qkvlo, g_qkvlo);
    cudaFuncSetAttribute((const void*)attn_mma,
                         cudaFuncAttributeMaxDynamicSharedMemorySize, ATTN_SMEM);

    const int QW4 = (3 * CC * CC) / 4;
    const int PW4 = (CC * CC) / 4;
    const int X4  = (int)(X_ELEMS / 4);
    const int PW_OFF = 3 * CC * CC;

    split_f32<<<(QW4 + 255) / 256, 256>>>(qkv_w, whi, wlo, QW4);
    split_f32<<<(PW4 + 255) / 256, 256>>>(proj_w, whi + PW_OFF, wlo + PW_OFF, PW4);
    split_f32<<<(X4 + 255) / 256, 256>>>(x, xhi, xlo, X4);

    // 1) qkv = W_qkv @ x + b  -> bf16 hi/lo
    gemm_bf16<false, true><<<dim3(T_LEN / 128, (3 * CC) / 128, BATCH), 256>>>(
        whi, wlo, xhi, xlo, qkv_b, nullptr, nullptr, qkvhi, qkvlo, 3 * CC, T_LEN, CC);

    // 2) attention (writes bf16 hi/lo into xhi/xlo)
    attn_mma<<<dim3(T_LEN / BT2, NH, BATCH), 256, ATTN_SMEM>>>();

    // 3) out = x + W_proj @ att + b  (fp32 out)
    gemm_bf16<true, false><<<dim3(T_LEN / 128, CC / 128, BATCH), 256>>>(
        whi + PW_OFF, wlo + PW_OFF, xhi, xlo, proj_b, x, out, nullptr, nullptr, CC, T_LEN, CC);
}

// round 6
// speedup vs baseline: 2.9282x; 1.0409x over previous
#include <cuda_runtime.h>
#include <cuda_bf16.h>
#include <math.h>
#include <stdint.h>

#define CC     512
#define T_LEN  2048
#define BATCH  4
#define NH     8
#define HD     64

// Scratch (allocation-free rule: __device__ globals)
#define W_ELEMS (3 * CC * CC + CC * CC)             // qkv_w then proj_w
#define X_ELEMS ((size_t)BATCH * CC * T_LEN)
#define QKV_ELEMS ((size_t)BATCH * 3 * CC * T_LEN)
__device__ __nv_bfloat16 g_whi[W_ELEMS];
__device__ __nv_bfloat16 g_wlo[W_ELEMS];
__device__ __nv_bfloat16 g_xhi[X_ELEMS];            // x split, later attn output split
__device__ __nv_bfloat16 g_xlo[X_ELEMS];
__device__ __nv_bfloat16 g_qkvhi[QKV_ELEMS];        // QKV GEMM output (hi/lo)
__device__ __nv_bfloat16 g_qkvlo[QKV_ELEMS];

// ===========================================================================
// helpers
// ===========================================================================
__device__ __forceinline__ uint32_t smem_u32(const void* p) {
    uint32_t a;
    asm("{ .reg .u64 t; cvta.to.shared.u64 t, %1; cvt.u32.u64 %0, t; }" : "=r"(a) : "l"(p));
    return a;
}
__device__ __forceinline__ uint32_t pk_bf2(__nv_bfloat16 a, __nv_bfloat16 b) {
    __nv_bfloat162 t(a, b);
    return *reinterpret_cast<uint32_t*>(&t);
}
__device__ __forceinline__ void split2(float x, float y, uint32_t& hi, uint32_t& lo) {
    __nv_bfloat16 xh = __float2bfloat16(x), yh = __float2bfloat16(y);
    __nv_bfloat16 xl = __float2bfloat16(x - __bfloat162float(xh));
    __nv_bfloat16 yl = __float2bfloat16(y - __bfloat162float(yh));
    hi = pk_bf2(xh, yh);
    lo = pk_bf2(xl, yl);
}
__device__ __forceinline__ void ldsm4(uint32_t& r0, uint32_t& r1, uint32_t& r2, uint32_t& r3,
                                      uint32_t addr) {
    asm volatile("ldmatrix.sync.aligned.m8n8.x4.shared.b16 {%0,%1,%2,%3}, [%4];"
                 : "=r"(r0), "=r"(r1), "=r"(r2), "=r"(r3) : "r"(addr));
}
__device__ __forceinline__ void ldsm4t(uint32_t& r0, uint32_t& r1, uint32_t& r2, uint32_t& r3,
                                       uint32_t addr) {
    asm volatile("ldmatrix.sync.aligned.m8n8.x4.trans.shared.b16 {%0,%1,%2,%3}, [%4];"
                 : "=r"(r0), "=r"(r1), "=r"(r2), "=r"(r3) : "r"(addr));
}
__device__ __forceinline__ void mma16816(float* c, uint32_t a0, uint32_t a1, uint32_t a2,
                                         uint32_t a3, uint32_t b0, uint32_t b1) {
    asm volatile(
        "mma.sync.aligned.m16n8k16.row.col.f32.bf16.bf16.f32 "
        "{%0,%1,%2,%3}, {%4,%5,%6,%7}, {%8,%9}, {%0,%1,%2,%3};"
        : "+f"(c[0]), "+f"(c[1]), "+f"(c[2]), "+f"(c[3])
        : "r"(a0), "r"(a1), "r"(a2), "r"(a3), "r"(b0), "r"(b1));
}
__device__ __forceinline__ void cp16(uint32_t dst, const void* src) {
    asm volatile("cp.async.cg.shared.global [%0], [%1], 16;" :: "r"(dst), "l"(src));
}
#define CP_COMMIT() asm volatile("cp.async.commit_group;" ::: "memory")
#define CP_WAIT0()  asm volatile("cp.async.wait_group 0;" ::: "memory")

// ===========================================================================
// prep: fp32 -> bf16 hi/lo split
// ===========================================================================
__global__ void __launch_bounds__(256) split_f32(
    const float* __restrict__ src, __nv_bfloat16* __restrict__ hi,
    __nv_bfloat16* __restrict__ lo, int n4)
{
    int i = blockIdx.x * blockDim.x + threadIdx.x;
    if (i >= n4) return;
    float4 v = ((const float4*)src)[i];
    uint32_t h0, l0, h1, l1;
    split2(v.x, v.y, h0, l0);
    split2(v.z, v.w, h1, l1);
    ((uint2*)hi)[i] = make_uint2(h0, h1);
    ((uint2*)lo)[i] = make_uint2(l0, l1);
}

// ===========================================================================
// bf16 3-term GEMM, tile 128x128x32, 8 warps (4M x 2N), cp.async 2-stage
// ===========================================================================
#define ASTR 80
#define BSTR 272
#define SA_HI 0
#define SA_LO 10240
#define SB_HI 20480
#define SB_LO 29184
#define GSTAGE 37888
#define GEMM_SMEM (2 * GSTAGE)

template<bool RES, bool SPLITOUT>
__global__ void __launch_bounds__(256, 2) gemm_bf16(
    const __nv_bfloat16* __restrict__ Ahi, const __nv_bfloat16* __restrict__ Alo,
    const __nv_bfloat16* __restrict__ Bhi, const __nv_bfloat16* __restrict__ Blo,
    const float* __restrict__ bias, const float* __restrict__ res,
    float* __restrict__ C, __nv_bfloat16* __restrict__ Chi, __nv_bfloat16* __restrict__ Clo,
    int M, int N, int K)
{
    extern __shared__ char sm[];
    const int z  = blockIdx.z;
    const int n0 = blockIdx.x * 128;
    const int m0 = blockIdx.y * 128;
    const int tid  = threadIdx.x;
    const int wid  = tid >> 5;
    const int lane = tid & 31;
    const int wm = wid & 3;
    const int wn = wid >> 2;

    const __nv_bfloat16* Bhz = Bhi + (size_t)z * K * N;
    const __nv_bfloat16* Blz = Blo + (size_t)z * K * N;

    float acc[2][8][4];
#pragma unroll
    for (int i = 0; i < 2; i++)
#pragma unroll
        for (int j = 0; j < 8; j++)
#pragma unroll
            for (int e = 0; e < 4; e++) acc[i][j][e] = 0.f;

    const uint32_t smb = smem_u32(sm);
    const int lr = lane & 15;
    const int lc = lane >> 4;
    const uint32_t aRel = SA_HI + (uint32_t)(wm * 32 + lr) * ASTR + lc * 16;
    const uint32_t bRel = SB_HI + (uint32_t)lr * BSTR + wn * 128 + lc * 16;

    // per-thread load coords
    const int am = tid >> 2, ak = (tid & 3) << 3;
    const int bk = tid >> 4, bn = (tid & 15) << 3;
    const int am2 = (tid + 256) >> 2, ak2 = ((tid + 256) & 3) << 3;
    const int bk2 = (tid + 256) >> 4, bn2 = ((tid + 256) & 15) << 3;

    const int KS = K >> 5;

    auto load_slab = [&](int k0, int st) {
        uint32_t base = smb + (uint32_t)st * GSTAGE;
        size_t ga  = (size_t)(m0 + am)  * K + k0 + ak;
        size_t ga2 = (size_t)(m0 + am2) * K + k0 + ak2;
        size_t gb  = (size_t)(k0 + bk)  * N + n0 + bn;
        size_t gb2 = (size_t)(k0 + bk2) * N + n0 + bn2;
        cp16(base + SA_HI + am * ASTR + ak * 2,  Ahi + ga);
        cp16(base + SA_LO + am * ASTR + ak * 2,  Alo + ga);
        cp16(base + SA_HI + am2 * ASTR + ak2 * 2, Ahi + ga2);
        cp16(base + SA_LO + am2 * ASTR + ak2 * 2, Alo + ga2);
        cp16(base + SB_HI + bk * BSTR + bn * 2,  Bhz + gb);
        cp16(base + SB_LO + bk * BSTR + bn * 2,  Blz + gb);
        cp16(base + SB_HI + bk2 * BSTR + bn2 * 2, Bhz + gb2);
        cp16(base + SB_LO + bk2 * BSTR + bn2 * 2, Blz + gb2);
    };

    load_slab(0, 0);
    CP_COMMIT();

    int stage = 0;
    for (int it = 0; it < KS; ++it) {
        CP_WAIT0();
        __syncthreads();
        if (it + 1 < KS) { load_slab((it + 1) << 5, stage ^ 1); CP_COMMIT(); }

        const uint32_t stb = (uint32_t)stage * GSTAGE;
        const uint32_t aAddr = smb + stb + aRel;
        const uint32_t bAddr = smb + stb + bRel;
#pragma unroll
        for (int ks = 0; ks < 2; ++ks) {
            uint32_t bh[4][4], bl[4][4];
#pragma unroll
            for (int g = 0; g < 4; ++g) {
                uint32_t base = bAddr + ks * (16 * BSTR) + g * 32;
                ldsm4t(bh[g][0], bh[g][1], bh[g][2], bh[g][3], base);
                ldsm4t(bl[g][0], bl[g][1], bl[g][2], bl[g][3], base + (SB_LO - SB_HI));
            }
#pragma unroll
            for (int mt = 0; mt < 2; ++mt) {
                uint32_t abase = aAddr + mt * (16 * ASTR) + ks * 32;
                uint32_t ah0, ah1, ah2, ah3, al0, al1, al2, al3;
                ldsm4(ah0, ah1, ah2, ah3, abase);
                ldsm4(al0, al1, al2, al3, abase + (SA_LO - SA_HI));
#pragma unroll
                for (int g = 0; g < 4; ++g) {
                    float* c0 = acc[mt][2 * g];
                    float* c1 = acc[mt][2 * g + 1];
                    mma16816(c0, ah0, ah1, ah2, ah3, bh[g][0], bh[g][1]);
                    mma16816(c0, ah0, ah1, ah2, ah3, bl[g][0], bl[g][1]);
                    mma16816(c0, al0, al1, al2, al3, bh[g][0], bh[g][1]);
                    mma16816(c1, ah0, ah1, ah2, ah3, bh[g][2], bh[g][3]);
                    mma16816(c1, ah0, ah1, ah2, ah3, bl[g][2], bl[g][3]);
                    mma16816(c1, al0, al1, al2, al3, bh[g][2], bh[g][3]);
                }
            }
        }
        stage ^= 1;
    }

#pragma unroll
    for (int mt = 0; mt < 2; ++mt) {
        int r1 = m0 + wm * 32 + mt * 16 + (lane >> 2);
        int r2 = r1 + 8;
        float b1 = bias[r1];
        float b2 = bias[r2];
#pragma unroll
        for (int g = 0; g < 8; ++g) {
            int col = n0 + wn * 64 + g * 8 + ((lane & 3) << 1);
            float2 w1 = make_float2(acc[mt][g][0] + b1, acc[mt][g][1] + b1);
            float2 w2 = make_float2(acc[mt][g][2] + b2, acc[mt][g][3] + b2);
            if (SPLITOUT) {
                __nv_bfloat16* ChZ = Chi + (size_t)z * M * N;
                __nv_bfloat16* ClZ = Clo + (size_t)z * M * N;
                uint32_t hh, ll;
                split2(w1.x, w1.y, hh, ll);
                *(uint32_t*)(ChZ + (size_t)r1 * N + col) = hh;
                *(uint32_t*)(ClZ + (size_t)r1 * N + col) = ll;
                split2(w2.x, w2.y, hh, ll);
                *(uint32_t*)(ChZ + (size_t)r2 * N + col) = hh;
                *(uint32_t*)(ClZ + (size_t)r2 * N + col) = ll;
            } else {
                float* Cz = C + (size_t)z * M * N;
                if (RES) {
                    float2 q1 = *(const float2*)(res + (size_t)z * M * N + (size_t)r1 * N + col);
                    float2 q2 = *(const float2*)(res + (size_t)z * M * N + (size_t)r2 * N + col);
                    w1.x += q1.x; w1.y += q1.y;
                    w2.x += q2.x; w2.y += q2.y;
                }
                *(float2*)(Cz + (size_t)r1 * N + col) = w1;
                *(float2*)(Cz + (size_t)r2 * N + col) = w2;
            }
        }
    }
}

// ===========================================================================
// Attention: mma.sync bf16 3-term, cp.async 2-stage K/V pipeline
// ===========================================================================
#define BT2 128
#define BS2 64
#define NIT (T_LEN / BS2)

#define QSTR 272
#define KSTR 144
#define SM_QHI 0
#define SM_QLO 17408
#define SM_KV  34816
#define KVS_K_HI 0
#define KVS_K_LO 9216
#define KVS_V_HI 18432
#define KVS_V_LO 27648
#define KVSTAGE 36864
#define ATTN_SMEM (SM_KV + 2 * KVSTAGE)    // 108544

__global__ void __launch_bounds__(256, 2) attn_mma()
{
    extern __shared__ char sm[];
    const int tid  = threadIdx.x;
    const int wid  = tid >> 5;
    const int lane = tid & 31;
    const int t0 = blockIdx.x * BT2;
    const int h  = blockIdx.y;
    const int b  = blockIdx.z;

    const size_t qoff = ((size_t)b * 3 * CC + h * HD) * T_LEN;
    const __nv_bfloat16* qhi = g_qkvhi + qoff;
    const __nv_bfloat16* qlo = g_qkvlo + qoff;
    const __nv_bfloat16* khi = qhi + (size_t)CC * T_LEN;
    const __nv_bfloat16* klo = qlo + (size_t)CC * T_LEN;
    const __nv_bfloat16* vhi = khi + (size_t)CC * T_LEN;
    const __nv_bfloat16* vlo = klo + (size_t)CC * T_LEN;

    const uint32_t smb = smem_u32(sm);

    // K/V tile loader: [d=64][s=64] pure cp.async copies
    const int kvd = tid >> 3, kvc = tid & 7;
    const int kvd2 = (tid + 256) >> 3, kvc2 = (tid + 256) & 7;
    auto kv_load = [&](int s0, int st) {
        uint32_t base = smb + SM_KV + (uint32_t)st * KVSTAGE;
        size_t g  = (size_t)kvd * T_LEN + s0 + kvc * 8;
        size_t g2 = (size_t)kvd2 * T_LEN + s0 + kvc2 * 8;
        uint32_t o  = base + kvd * KSTR + kvc * 16;
        uint32_t o2 = base + kvd2 * KSTR + kvc2 * 16;
        cp16(o + KVS_K_HI,  khi + g);
        cp16(o + KVS_K_LO,  klo + g);
        cp16(o + KVS_V_HI,  vhi + g);
        cp16(o + KVS_V_LO,  vlo + g);
        cp16(o2 + KVS_K_HI, khi + g2);
        cp16(o2 + KVS_K_LO, klo + g2);
        cp16(o2 + KVS_V_HI, vhi + g2);
        cp16(o2 + KVS_V_LO, vlo + g2);
    };

    kv_load(0, 0);
    CP_COMMIT();

    // ---- Q tile [d=64][t=128]: pure copies (overlaps with first K/V load) ----
#pragma unroll
    for (int l = 0; l < 4; ++l) {
        int f = tid + l * 256;
        int d = f >> 4;
        int c = f & 15;
        size_t g = (size_t)d * T_LEN + t0 + c * 8;
        *(uint4*)(sm + SM_QHI + d * QSTR + c * 16) = *(const uint4*)(qhi + g);
        *(uint4*)(sm + SM_QLO + d * QSTR + c * 16) = *(const uint4*)(qlo + g);
    }

    float oacc[32];
#pragma unroll
    for (int i = 0; i < 32; ++i) oacc[i] = 0.f;
    float m_r1 = -INFINITY, m_r2 = -INFINITY, l_r1 = 0.f, l_r2 = 0.f;

    // A-frag (Q) trans-ldsm: rows=d, cols=t
    const int q8 = lane & 7;
    const int qh2 = (lane >> 3) & 1;
    const int qd2 = lane >> 4;
    const uint32_t qa_hi = smb + SM_QHI + (uint32_t)(q8 + 8 * qd2) * QSTR + wid * 32 + qh2 * 16;
    const uint32_t qa_lo = qa_hi + (SM_QLO - SM_QHI);
    // B-frag (K) trans-ldsm: rows=d(=k), cols=s
    const int lr = lane & 15;
    const int lc = lane >> 4;
    const uint32_t kb_rel = (uint32_t)lr * KSTR + lc * 16;              // + KVS_K_HI(0)
    // B-frag (V) non-trans: rows=d(=n), cols=s(=k)
    const int v8 = lane & 7;
    const int vh2 = (lane >> 3) & 1;
    const int vd2 = lane >> 4;
    const uint32_t vb_rel = KVS_V_HI + (uint32_t)(v8 + 8 * vd2) * KSTR + vh2 * 16;

    const float scale = 0.044194173824159216f;   // 512^-0.5

    int stage = 0;
    for (int it = 0; it < NIT; ++it) {
        CP_WAIT0();
        __syncthreads();
        if (it + 1 < NIT) { kv_load((it + 1) * BS2, stage ^ 1); CP_COMMIT(); }

        const uint32_t kvb = smb + SM_KV + (uint32_t)stage * KVSTAGE;
        const uint32_t kb_hi = kvb + kb_rel;
        const uint32_t kb_lo = kb_hi + KVS_K_LO;
        const uint32_t vb_hi = kvb + vb_rel;

        // ---- S = Q K^T ----
        float sacc[32];
#pragma unroll
        for (int i = 0; i < 32; ++i) sacc[i] = 0.f;
#pragma unroll
        for (int ks = 0; ks < 4; ++ks) {
            uint32_t qh0, qh1, qh2r, qh3, ql0, ql1, ql2, ql3;
            ldsm4t(qh0, qh1, qh2r, qh3, qa_hi + ks * (16 * QSTR));
            ldsm4t(ql0, ql1, ql2, ql3, qa_lo + ks * (16 * QSTR));
#pragma unroll
            for (int np = 0; np < 4; ++np) {
                uint32_t bh0, bh1, bh2, bh3, bl0, bl1, bl2, bl3;
                ldsm4t(bh0, bh1, bh2, bh3, kb_hi + ks * (16 * KSTR) + np * 32);
                ldsm4t(bl0, bl1, bl2, bl3, kb_lo + ks * (16 * KSTR) + np * 32);
                float* c0 = &sacc[np * 8];
                float* c1 = &sacc[np * 8 + 4];
                mma16816(c0, qh0, qh1, qh2r, qh3, bh0, bh1);
                mma16816(c0, qh0, qh1, qh2r, qh3, bl0, bl1);
                mma16816(c0, ql0, ql1, ql2, ql3, bh0, bh1);
                mma16816(c1, qh0, qh1, qh2r, qh3, bh2, bh3);
                mma16816(c1, qh0, qh1, qh2r, qh3, bl2, bl3);
                mma16816(c1, ql0, ql1, ql2, ql3, bh2, bh3);
            }
        }

        // ---- scale + online softmax ----
#pragma unroll
        for (int i = 0; i < 32; ++i) sacc[i] *= scale;
        float nm1 = -INFINITY, nm2 = -INFINITY;
#pragma unroll
        for (int j = 0; j < 8; ++j) {
            nm1 = fmaxf(nm1, fmaxf(sacc[4 * j],     sacc[4 * j + 1]));
            nm2 = fmaxf(nm2, fmaxf(sacc[4 * j + 2], sacc[4 * j + 3]));
        }
        nm1 = fmaxf(nm1, __shfl_xor_sync(0xffffffffu, nm1, 1));
        nm1 = fmaxf(nm1, __shfl_xor_sync(0xffffffffu, nm1, 2));
        nm2 = fmaxf(nm2, __shfl_xor_sync(0xffffffffu, nm2, 1));
        nm2 = fmaxf(nm2, __shfl_xor_sync(0xffffffffu, nm2, 2));
        const float mn1 = fmaxf(m_r1, nm1);
        const float mn2 = fmaxf(m_r2, nm2);
        const float a1 = __expf(m_r1 - mn1);
        const float a2 = __expf(m_r2 - mn2);
        float s1 = 0.f, s2 = 0.f;
#pragma unroll
        for (int j = 0; j < 8; ++j) {
            float e0 = __expf(sacc[4 * j]     - mn1);
            float e1 = __expf(sacc[4 * j + 1] - mn1);
            float e2 = __expf(sacc[4 * j + 2] - mn2);
            float e3 = __expf(sacc[4 * j + 3] - mn2);
            sacc[4 * j] = e0; sacc[4 * j + 1] = e1; sacc[4 * j + 2] = e2; sacc[4 * j + 3] = e3;
            s1 += e0 + e1;
            s2 += e2 + e3;
        }
        s1 += __shfl_xor_sync(0xffffffffu, s1, 1);
        s1 += __shfl_xor_sync(0xffffffffu, s1, 2);
        s2 += __shfl_xor_sync(0xffffffffu, s2, 1);
        s2 += __shfl_xor_sync(0xffffffffu, s2, 2);
        l_r1 = l_r1 * a1 + s1;
        l_r2 = l_r2 * a2 + s2;
        m_r1 = mn1;
        m_r2 = mn2;
#pragma unroll
        for (int j = 0; j < 8; ++j) {
            oacc[4 * j]     *= a1;
            oacc[4 * j + 1] *= a1;
            oacc[4 * j + 2] *= a2;
            oacc[4 * j + 3] *= a2;
        }

        // ---- O += P V^T ----
#pragma unroll
        for (int ks = 0; ks < 4; ++ks) {
            const float* sA = &sacc[8 * ks];
            uint32_t ph0, ph1, ph2, ph3, pl0, pl1, pl2, pl3;
            split2(sA[0], sA[1], ph0, pl0);
            split2(sA[2], sA[3], ph1, pl1);
            split2(sA[4], sA[5], ph2, pl2);
            split2(sA[6], sA[7], ph3, pl3);
#pragma unroll
            for (int np = 0; np < 4; ++np) {
                uint32_t bh0, bh1, bh2, bh3, bl0, bl1, bl2, bl3;
                uint32_t base = vb_hi + np * (16 * KSTR) + ks * 32;
                ldsm4(bh0, bh1, bh2, bh3, base);
                ldsm4(bl0, bl1, bl2, bl3, base + (KVS_V_LO - KVS_V_HI));
                float* c0 = &oacc[np * 8];
                float* c1 = &oacc[np * 8 + 4];
                mma16816(c0, ph0, ph1, ph2, ph3, bh0, bh1);
                mma16816(c0, ph0, ph1, ph2, ph3, bl0, bl1);
                mma16816(c0, pl0, pl1, pl2, pl3, bh0, bh1);
                mma16816(c1, ph0, ph1, ph2, ph3, bh2, bh3);
                mma16816(c1, ph0, ph1, ph2, ph3, bl2, bl3);
                mma16816(c1, pl0, pl1, pl2, pl3, bh2, bh3);
            }
        }
        stage ^= 1;
    }

    __syncthreads();
    // ---- epilogue: normalize, stage [d][t] fp32, write bf16 hi/lo split ----
    {
        float* so = (float*)(sm + SM_KV);
        const float i1 = 1.f / l_r1;
        const float i2 = 1.f / l_r2;
        const int r  = lane >> 2;
        const int tw = wid * 16;
#pragma unroll
        for (int j = 0; j < 8; ++j) {
            int d0 = 8 * j + ((lane & 3) << 1);
            so[(size_t)d0 * 128 + tw + r]           = oacc[4 * j]     * i1;
            so[(size_t)(d0 + 1) * 128 + tw + r]     = oacc[4 * j + 1] * i1;
            so[(size_t)d0 * 128 + tw + r + 8]       = oacc[4 * j + 2] * i2;
            so[(size_t)(d0 + 1) * 128 + tw + r + 8] = oacc[4 * j + 3] * i2;
        }
        __syncthreads();
        const size_t obase = ((size_t)b * CC + h * HD) * T_LEN;
#pragma unroll
        for (int l = 0; l < 8; ++l) {
            int f  = tid + l * 256;
            int c  = f >> 5;
            int t4 = (f & 31) << 2;
            float4 v = *(float4*)&so[(size_t)c * 128 + t4];
            uint32_t h0, l0, h1, l1;
            split2(v.x, v.y, h0, l0);
            split2(v.z, v.w, h1, l1);
            size_t g = obase + (size_t)c * T_LEN + t0 + t4;
            *(uint2*)(g_xhi + g) = make_uint2(h0, h1);
            *(uint2*)(g_xlo + g) = make_uint2(l0, l1);
        }
    }
}

// ===========================================================================
extern "C" void kernel_launch(void* const* d_in, const int* in_sizes, int n_in,
                              void* d_out, int out_size)
{
    const float* x      = (const float*)d_in[0];
    const float* qkv_w  = (const float*)d_in[1];
    const float* qkv_b  = (const float*)d_in[2];
    const float* proj_w = (const float*)d_in[3];
    const float* proj_b = (const float*)d_in[4];
    float* out = (float*)d_out;

    __nv_bfloat16 *whi, *wlo, *xhi, *xlo, *qkvhi, *qkvlo;
    cudaGetSymbolAddress((void**)&whi, g_whi);
    cudaGetSymbolAddress((void**)&wlo, g_wlo);
    cudaGetSymbolAddress((void**)&xhi, g_xhi);
    cudaGetSymbolAddress((void**)&xlo, g_xlo);
    cudaGetSymbolAddress((void**)&qkvhi, g_qkvhi);
    cudaGetSymbolAddress((void**)&qkvlo, g_qkvlo);

    cudaFuncSetAttribute((const void*)attn_mma,
                         cudaFuncAttributeMaxDynamicSharedMemorySize, ATTN_SMEM);
    cudaFuncSetAttribute((const void*)gemm_bf16<false, true>,
                         cudaFuncAttributeMaxDynamicSharedMemorySize, GEMM_SMEM);
    cudaFuncSetAttribute((const void*)gemm_bf16<true, false>,
                         cudaFuncAttributeMaxDynamicSharedMemorySize, GEMM_SMEM);

    const int QW4 = (3 * CC * CC) / 4;
    const int PW4 = (CC * CC) / 4;
    const int X4  = (int)(X_ELEMS / 4);
    const int PW_OFF = 3 * CC * CC;

    split_f32<<<(QW4 + 255) / 256, 256>>>(qkv_w, whi, wlo, QW4);
    split_f32<<<(PW4 + 255) / 256, 256>>>(proj_w, whi + PW_OFF, wlo + PW_OFF, PW4);
    split_f32<<<(X4 + 255) / 256, 256>>>(x, xhi, xlo, X4);

    // 1) qkv = W_qkv @ x + b  -> bf16 hi/lo
    gemm_bf16<false, true><<<dim3(T_LEN / 128, (3 * CC) / 128, BATCH), 256, GEMM_SMEM>>>(
        whi, wlo, xhi, xlo, qkv_b, nullptr, nullptr, qkvhi, qkvlo, 3 * CC, T_LEN, CC);

    // 2) attention (writes bf16 hi/lo into xhi/xlo)
    attn_mma<<<dim3(T_LEN / BT2, NH, BATCH), 256, ATTN_SMEM>>>();

    // 3) out = x + W_proj @ att + b  (fp32 out)
    gemm_bf16<true, false><<<dim3(T_LEN / 128, CC / 128, BATCH), 256, GEMM_SMEM>>>(
        whi + PW_OFF, wlo + PW_OFF, xhi, xlo, proj_b, x, out, nullptr, nullptr, CC, T_LEN, CC);
}